// round 6
// baseline (speedup 1.0000x reference)
#include <cuda_runtime.h>
#include <cstdint>
#include <math.h>

#define BATCH 32
#define HEADS 32
#define KVHEADS 8
#define DIM 128
#define KCTX 4096
#define HSZ 4096
#define GRP 4
#define NSPLIT 16
#define KSG 16                     // gemm k-splits
#define QK_SCALE 0.08838834764831845f
#define M_FIX 16.0f                // fixed softmax shift (scale-invariant)

// ------------------------------ scratch (no allocs allowed) ------------------
__device__ float g_q[BATCH * HSZ];                              // 512 KB
__device__ float g_attn[BATCH * HSZ];                           // 512 KB
__device__ float g_gpart[KSG * BATCH * HSZ];                    // 8 MB (gemm split-K partials)
__device__ float g_pacc[BATCH * KVHEADS * NSPLIT * GRP * DIM];  // 8 MB (attn partials)
__device__ float g_pl[BATCH * KVHEADS * NSPLIT * GRP];

// ------------------------------ GEMM: out[b,n] = sum_k A[b,k] * W[n,k] -------
__global__ __launch_bounds__(256) void gemm_tn(const float* __restrict__ A,
                                               const float* __restrict__ W) {
    __shared__ float As[32][36];    // [kk][bb], padded
    __shared__ float Ws[32][260];   // [kk][nn], padded
    const int tid = threadIdx.x;
    const int tx = tid & 31;        // n lane
    const int ty = tid >> 5;        // b group (0..7)
    const int n0 = blockIdx.x * 256;
    const int ks = blockIdx.y;

    float acc[4][8] = {};

    const int kbeg = ks * (HSZ / KSG);
    for (int kb = kbeg; kb < kbeg + (HSZ / KSG); kb += 32) {
        __syncthreads();
        {
            int bb = tid >> 3, kk4 = tid & 7;
            float4 a = *(const float4*)&A[bb * HSZ + kb + kk4 * 4];
            As[kk4 * 4 + 0][bb] = a.x;
            As[kk4 * 4 + 1][bb] = a.y;
            As[kk4 * 4 + 2][bb] = a.z;
            As[kk4 * 4 + 3][bb] = a.w;
        }
        #pragma unroll
        for (int r = 0; r < 8; r++) {
            int idx = tid + 256 * r;
            int nn = idx >> 3, kk4 = idx & 7;
            float4 wv = *(const float4*)&W[(size_t)(n0 + nn) * HSZ + kb + kk4 * 4];
            Ws[kk4 * 4 + 0][nn] = wv.x;
            Ws[kk4 * 4 + 1][nn] = wv.y;
            Ws[kk4 * 4 + 2][nn] = wv.z;
            Ws[kk4 * 4 + 3][nn] = wv.w;
        }
        __syncthreads();
        #pragma unroll
        for (int kk = 0; kk < 32; kk++) {
            float4 av = *(const float4*)&As[kk][ty * 4];
            float4 w0 = *(const float4*)&Ws[kk][tx * 4];
            float4 w1 = *(const float4*)&Ws[kk][128 + tx * 4];
            float a4[4] = {av.x, av.y, av.z, av.w};
            float w8[8] = {w0.x, w0.y, w0.z, w0.w, w1.x, w1.y, w1.z, w1.w};
            #pragma unroll
            for (int jj = 0; jj < 4; jj++)
                #pragma unroll
                for (int ii = 0; ii < 8; ii++)
                    acc[jj][ii] = fmaf(a4[jj], w8[ii], acc[jj][ii]);
        }
    }

    float* outp = g_gpart + (size_t)ks * (BATCH * HSZ);
    #pragma unroll
    for (int jj = 0; jj < 4; jj++) {
        float4 o0 = make_float4(acc[jj][0], acc[jj][1], acc[jj][2], acc[jj][3]);
        float4 o1 = make_float4(acc[jj][4], acc[jj][5], acc[jj][6], acc[jj][7]);
        *(float4*)&outp[(size_t)(ty * 4 + jj) * HSZ + n0 + tx * 4] = o0;
        *(float4*)&outp[(size_t)(ty * 4 + jj) * HSZ + n0 + 128 + tx * 4] = o1;
    }
}

// sum the KSG split-K partials into dst. 131072 elems.
__global__ void ksum_part(float* __restrict__ dst) {
    int i = blockIdx.x * blockDim.x + threadIdx.x;
    float s = 0.f;
    #pragma unroll
    for (int p = 0; p < KSG; p++) s += g_gpart[(size_t)p * (BATCH * HSZ) + i];
    dst[i] = s;
}

// ------------------------------ RoPE (in-place on g_q) ----------------------
__global__ void rope_kernel(const int* __restrict__ positions) {
    const int bh = blockIdx.x;
    const int b = bh >> 5;
    const int j = threadIdx.x;           // 0..63
    double inv = exp(-(double)j * (13.815510557964274 / 64.0));
    double ang = (double)positions[b] * inv;
    double sd, cd;
    sincos(ang, &sd, &cd);
    float c = (float)cd, s = (float)sd;
    float* qp = g_q + ((size_t)bh << 7);
    float q1 = qp[j], q2 = qp[j + 64];
    qp[j]      = q1 * c - q2 * s;
    qp[j + 64] = q2 * c + q1 * s;
}

// ------------------------------ attention ----------------------------------
// grid = B*KVH*NSPLIT (4096), block 128 (4 warps). 16 lanes per key, 2 keys
// per warp-iteration (half-warp groups). Fixed-shift softmax (scale-invariant).
// Warp w of split s owns pair-bases j = s + 16w + 128i; group A = key j,
// group B = key j+64.
__global__ __launch_bounds__(128, 6) void attn_kernel(const float* __restrict__ kc,
                                                      const float* __restrict__ vc,
                                                      const int* __restrict__ clens) {
    const int blk = blockIdx.x;
    const int split = blk & 15;
    const int kvh = (blk >> 4) & 7;
    const int b = blk >> 7;
    const int tid = threadIdx.x;
    const int wid = tid >> 5;
    const int lane = tid & 31;
    const int lane16 = lane & 15;
    const int hoff = (lane >> 4) << 6;   // 0 or 64: which key of the pair

    __shared__ float qs[GRP * DIM];
    __shared__ float sl[8][GRP];
    __shared__ float sacc[8][GRP][DIM];

    // load q (scale folded in)
    for (int idx = tid; idx < GRP * DIM; idx += 128)
        qs[idx] = g_q[((size_t)(b * HEADS + kvh * GRP) << 7) + idx] * QK_SCALE;
    __syncthreads();

    unsigned int qaddr;   // smem byte addr of this lane's first q chunk
    {
        const float* qp = qs + lane16 * 4;
        asm("{ .reg .u64 t; cvta.to.shared.u64 t, %1; cvt.u32.u64 %0, t; }"
            : "=r"(qaddr) : "l"(qp));
    }

    const int ctx = clens[b];
    const size_t rs = (size_t)KVHEADS * DIM; // 1024 floats per key index
    // lane's chunks: dims [lane16*4, +4) and [64+lane16*4, +4)
    const float* kp = kc + (size_t)b * KCTX * rs + (size_t)kvh * DIM + lane16 * 4;
    const float* vp = vc + (size_t)b * KCTX * rs + (size_t)kvh * DIM + lane16 * 4;

    float l[4] = {0.f, 0.f, 0.f, 0.f};
    float4 a0[4], a1[4];
    #pragma unroll
    for (int g = 0; g < 4; g++) {
        a0[g] = make_float4(0.f, 0.f, 0.f, 0.f);
        a1[g] = make_float4(0.f, 0.f, 0.f, 0.f);
    }

#define LOADK(KA, KB, JB)                                                      \
    do {                                                                       \
        int idc_ = min((JB) + hoff, ctx - 1);                                  \
        const float* kr_ = kp + (size_t)idc_ * rs;                             \
        KA = *(const float4*)kr_;                                              \
        KB = *(const float4*)(kr_ + 64);                                       \
    } while (0)

#define STEP(KA, KB, JB)                                                       \
    do {                                                                       \
        int idx_ = (JB) + hoff;                                                \
        int idc_ = min(idx_, ctx - 1);                                         \
        const float* vr_ = vp + (size_t)idc_ * rs;                             \
        float4 v0_ = *(const float4*)vr_;                                      \
        float4 v1_ = *(const float4*)(vr_ + 64);                               \
        float vf_ = (idx_ < ctx) ? 1.f : 0.f;                                  \
        float sv[4];                                                           \
        _Pragma("unroll")                                                      \
        for (int g = 0; g < 4; g++) {                                          \
            float qx, qy, qz, qw, rx, ry, rz, rw;                              \
            asm volatile("ld.shared.v4.f32 {%0,%1,%2,%3}, [%4];"               \
                         : "=f"(qx), "=f"(qy), "=f"(qz), "=f"(qw)              \
                         : "r"(qaddr + g * 512));                              \
            asm volatile("ld.shared.v4.f32 {%0,%1,%2,%3}, [%4];"               \
                         : "=f"(rx), "=f"(ry), "=f"(rz), "=f"(rw)              \
                         : "r"(qaddr + g * 512 + 256));                        \
            float s0 = fmaf(qx, KA.x, fmaf(qy, KA.y, fmaf(qz, KA.z, qw * KA.w))); \
            float s1 = fmaf(rx, KB.x, fmaf(ry, KB.y, fmaf(rz, KB.z, rw * KB.w))); \
            sv[g] = s0 + s1;                                                   \
        }                                                                      \
        _Pragma("unroll")                                                      \
        for (int off = 8; off > 0; off >>= 1) {                                \
            sv[0] += __shfl_xor_sync(0xffffffffu, sv[0], off);                 \
            sv[1] += __shfl_xor_sync(0xffffffffu, sv[1], off);                 \
            sv[2] += __shfl_xor_sync(0xffffffffu, sv[2], off);                 \
            sv[3] += __shfl_xor_sync(0xffffffffu, sv[3], off);                 \
        }                                                                      \
        _Pragma("unroll")                                                      \
        for (int g = 0; g < 4; g++) {                                          \
            float p = __expf(sv[g] - M_FIX) * vf_;                             \
            l[g] += p;                                                         \
            a0[g].x = fmaf(p, v0_.x, a0[g].x);                                 \
            a0[g].y = fmaf(p, v0_.y, a0[g].y);                                 \
            a0[g].z = fmaf(p, v0_.z, a0[g].z);                                 \
            a0[g].w = fmaf(p, v0_.w, a0[g].w);                                 \
            a1[g].x = fmaf(p, v1_.x, a1[g].x);                                 \
            a1[g].y = fmaf(p, v1_.y, a1[g].y);                                 \
            a1[g].z = fmaf(p, v1_.z, a1[g].z);                                 \
            a1[g].w = fmaf(p, v1_.w, a1[g].w);                                 \
        }                                                                      \
    } while (0)

    int j = split + 16 * wid;    // pair base; pair covers keys j and j+64
    if (j < ctx) {
        float4 k00, k01, k10, k11;   // 2-stage K ring (V loaded at compute)
        LOADK(k00, k01, j);
        if (j + 128 < ctx) LOADK(k10, k11, j + 128);
        for (;;) {
            STEP(k00, k01, j);
            j += 128;
            if (j >= ctx) break;
            if (j + 128 < ctx) LOADK(k00, k01, j + 128);
            STEP(k10, k11, j);
            j += 128;
            if (j >= ctx) break;
            if (j + 128 < ctx) LOADK(k10, k11, j + 128);
        }
    }
#undef LOADK
#undef STEP

    // stash per-half-warp partials (both halves cover all dims, distinct keys)
    const int slot = (wid << 1) + (lane >> 4);   // 0..7
    if (lane16 == 0) {
        #pragma unroll
        for (int g = 0; g < 4; g++) sl[slot][g] = l[g];
    }
    #pragma unroll
    for (int g = 0; g < 4; g++) {
        *(float4*)(&sacc[slot][g][lane16 * 4]) = a0[g];
        *(float4*)(&sacc[slot][g][64 + lane16 * 4]) = a1[g];
    }
    __syncthreads();

    // combine the 8 half-warp partials: thread group per g, float4 per thread
    const int g = tid >> 5;
    const int l32 = tid & 31;
    float L = 0.f;
    float4 V = make_float4(0.f, 0.f, 0.f, 0.f);
    #pragma unroll
    for (int w = 0; w < 8; w++) {
        L += sl[w][g];
        float4 a = *(const float4*)(&sacc[w][g][l32 * 4]);
        V.x += a.x; V.y += a.y; V.z += a.z; V.w += a.w;
    }
    const size_t pb = (size_t)(blk * GRP + g) * DIM;
    *(float4*)&g_pacc[pb + l32 * 4] = V;
    if (l32 == 0) g_pl[blk * GRP + g] = L;
}

// combine NSPLIT partials -> g_attn[b, h, d]. grid = B*KVH*G (1024), block 128.
__global__ void attn_reduce() {
    const int idx = blockIdx.x;
    const int g = idx & 3;
    const int kvh = (idx >> 2) & 7;
    const int b = idx >> 5;
    const int d = threadIdx.x;
    const int base = ((b * KVHEADS + kvh) * NSPLIT) * GRP + g;
    float L = 0.f, a = 0.f;
    #pragma unroll
    for (int s = 0; s < NSPLIT; s++) {
        L += g_pl[base + s * GRP];
        a += g_pacc[(size_t)(base + s * GRP) * DIM + d];
    }
    g_attn[((size_t)(b * HEADS + kvh * GRP + g) << 7) + d] = a / L;
}

// ------------------------------ launch --------------------------------------
extern "C" void kernel_launch(void* const* d_in, const int* in_sizes, int n_in,
                              void* d_out, int out_size) {
    const float* hs = (const float*)d_in[0];
    const int* pos = (const int*)d_in[1];
    const float* kc = (const float*)d_in[2];
    const float* vc = (const float*)d_in[3];
    const int* cl = (const int*)d_in[4];
    const float* wq = (const float*)d_in[5];
    const float* wo = (const float*)d_in[6];
    float* out = (float*)d_out;

    float* qbuf = nullptr;
    float* abuf = nullptr;
    cudaGetSymbolAddress((void**)&qbuf, g_q);
    cudaGetSymbolAddress((void**)&abuf, g_attn);

    // q = hs @ wq.T
    gemm_tn<<<dim3(16, KSG), 256>>>(hs, wq);
    ksum_part<<<512, 256>>>(qbuf);
    // RoPE in place
    rope_kernel<<<1024, 64>>>(pos);
    // flash-decode attention, strided split over K
    attn_kernel<<<BATCH * KVHEADS * NSPLIT, 128>>>(kc, vc, cl);
    attn_reduce<<<BATCH * KVHEADS * GRP, 128>>>();
    // out = attn @ wo.T
    gemm_tn<<<dim3(16, KSG), 256>>>(abuf, wo);
    ksum_part<<<512, 256>>>(out);
}

// round 7
// speedup vs baseline: 1.4671x; 1.4671x over previous
#include <cuda_runtime.h>
#include <cstdint>
#include <math.h>

#define BATCH 32
#define HEADS 32
#define KVHEADS 8
#define DIM 128
#define KCTX 4096
#define HSZ 4096
#define GRP 4
#define NSPLIT 16
#define KSG 16                     // gemm k-splits
#define QK_SCALE 0.08838834764831845f
#define M_FIX 16.0f                // fixed softmax shift (scale-invariant)

// ------------------------------ scratch (no allocs allowed) ------------------
__device__ float g_q[BATCH * HSZ];                              // 512 KB
__device__ float g_attn[BATCH * HSZ];                           // 512 KB
__device__ float g_gpart[KSG * BATCH * HSZ];                    // 8 MB (gemm split-K partials)
__device__ float g_pacc[BATCH * KVHEADS * NSPLIT * GRP * DIM];  // 8 MB (attn partials)
__device__ float g_pl[BATCH * KVHEADS * NSPLIT * GRP];

// ------------------------------ GEMM: out[b,n] = sum_k A[b,k] * W[n,k] -------
__global__ __launch_bounds__(256) void gemm_tn(const float* __restrict__ A,
                                               const float* __restrict__ W) {
    __shared__ float As[32][36];    // [kk][bb], padded
    __shared__ float Ws[32][260];   // [kk][nn], padded
    const int tid = threadIdx.x;
    const int tx = tid & 31;        // n lane
    const int ty = tid >> 5;        // b group (0..7)
    const int n0 = blockIdx.x * 256;
    const int ks = blockIdx.y;

    float acc[4][8] = {};

    const int kbeg = ks * (HSZ / KSG);
    for (int kb = kbeg; kb < kbeg + (HSZ / KSG); kb += 32) {
        __syncthreads();
        {
            int bb = tid >> 3, kk4 = tid & 7;
            float4 a = *(const float4*)&A[bb * HSZ + kb + kk4 * 4];
            As[kk4 * 4 + 0][bb] = a.x;
            As[kk4 * 4 + 1][bb] = a.y;
            As[kk4 * 4 + 2][bb] = a.z;
            As[kk4 * 4 + 3][bb] = a.w;
        }
        #pragma unroll
        for (int r = 0; r < 8; r++) {
            int idx = tid + 256 * r;
            int nn = idx >> 3, kk4 = idx & 7;
            float4 wv = *(const float4*)&W[(size_t)(n0 + nn) * HSZ + kb + kk4 * 4];
            Ws[kk4 * 4 + 0][nn] = wv.x;
            Ws[kk4 * 4 + 1][nn] = wv.y;
            Ws[kk4 * 4 + 2][nn] = wv.z;
            Ws[kk4 * 4 + 3][nn] = wv.w;
        }
        __syncthreads();
        #pragma unroll
        for (int kk = 0; kk < 32; kk++) {
            float4 av = *(const float4*)&As[kk][ty * 4];
            float4 w0 = *(const float4*)&Ws[kk][tx * 4];
            float4 w1 = *(const float4*)&Ws[kk][128 + tx * 4];
            float a4[4] = {av.x, av.y, av.z, av.w};
            float w8[8] = {w0.x, w0.y, w0.z, w0.w, w1.x, w1.y, w1.z, w1.w};
            #pragma unroll
            for (int jj = 0; jj < 4; jj++)
                #pragma unroll
                for (int ii = 0; ii < 8; ii++)
                    acc[jj][ii] = fmaf(a4[jj], w8[ii], acc[jj][ii]);
        }
    }

    float* outp = g_gpart + (size_t)ks * (BATCH * HSZ);
    #pragma unroll
    for (int jj = 0; jj < 4; jj++) {
        float4 o0 = make_float4(acc[jj][0], acc[jj][1], acc[jj][2], acc[jj][3]);
        float4 o1 = make_float4(acc[jj][4], acc[jj][5], acc[jj][6], acc[jj][7]);
        *(float4*)&outp[(size_t)(ty * 4 + jj) * HSZ + n0 + tx * 4] = o0;
        *(float4*)&outp[(size_t)(ty * 4 + jj) * HSZ + n0 + 128 + tx * 4] = o1;
    }
}

// sum the KSG split-K partials into dst. 131072 elems.
__global__ void ksum_part(float* __restrict__ dst) {
    int i = blockIdx.x * blockDim.x + threadIdx.x;
    float s = 0.f;
    #pragma unroll
    for (int p = 0; p < KSG; p++) s += g_gpart[(size_t)p * (BATCH * HSZ) + i];
    dst[i] = s;
}

// ------------------------------ RoPE (in-place on g_q) ----------------------
__global__ void rope_kernel(const int* __restrict__ positions) {
    const int bh = blockIdx.x;
    const int b = bh >> 5;
    const int j = threadIdx.x;           // 0..63
    double inv = exp(-(double)j * (13.815510557964274 / 64.0));
    double ang = (double)positions[b] * inv;
    double sd, cd;
    sincos(ang, &sd, &cd);
    float c = (float)cd, s = (float)sd;
    float* qp = g_q + ((size_t)bh << 7);
    float q1 = qp[j], q2 = qp[j + 64];
    qp[j]      = q1 * c - q2 * s;
    qp[j + 64] = q2 * c + q1 * s;
}

// ------------------------------ attention ----------------------------------
// grid = B*KVH*NSPLIT (4096), block 128 (4 warps). Full warp per key (one
// coalesced 512B row per LDGSTS/LDS). cp.async depth-4 smem ring per warp:
// 4 KB in flight per warp with zero staging registers. q lives in registers.
// Fixed-shift softmax (scale-invariant): p = exp(s - M_FIX), no max tracking.
__global__ __launch_bounds__(128, 8) void attn_kernel(const float* __restrict__ kc,
                                                      const float* __restrict__ vc,
                                                      const int* __restrict__ clens) {
    const int blk = blockIdx.x;
    const int split = blk & 15;
    const int kvh = (blk >> 4) & 7;
    const int b = blk >> 7;
    const int tid = threadIdx.x;
    const int wid = tid >> 5;
    const int lane = tid & 31;

    __shared__ float4 ring[4][4][64];   // [warp][stage][K:0-31 | V:32-63]  16 KB
    __shared__ float sl[4][GRP];
    __shared__ float sacc[4][GRP][DIM]; // 8 KB

    // q into registers (scale folded in): lane owns dims [lane*4, lane*4+4)
    float4 q[GRP];
    {
        const float* qg = g_q + ((size_t)(b * HEADS + kvh * GRP) << 7) + lane * 4;
        #pragma unroll
        for (int g = 0; g < GRP; g++) {
            float4 t = *(const float4*)(qg + g * DIM);
            q[g].x = t.x * QK_SCALE; q[g].y = t.y * QK_SCALE;
            q[g].z = t.z * QK_SCALE; q[g].w = t.w * QK_SCALE;
        }
    }

    const int ctx = clens[b];
    const size_t rs = (size_t)KVHEADS * DIM; // 1024 floats per key index
    const float* kp = kc + (size_t)b * KCTX * rs + (size_t)kvh * DIM + lane * 4;
    const float* vp = vc + (size_t)b * KCTX * rs + (size_t)kvh * DIM + lane * 4;

    float l[4] = {0.f, 0.f, 0.f, 0.f};
    float4 acc[4];
    #pragma unroll
    for (int g = 0; g < 4; g++) acc[g] = make_float4(0.f, 0.f, 0.f, 0.f);

    const unsigned rb =
        (unsigned)__cvta_generic_to_shared(&ring[wid][0][0]) + lane * 16u;

    const int j0 = split + 16 * wid;   // this warp's first key; stride 64

    // prologue: stages 0..2 (clamped addresses are always valid; only in-range
    // keys are ever consumed, so clamping never affects results)
    #pragma unroll
    for (int s = 0; s < 3; s++) {
        int jc = min(j0 + 64 * s, ctx - 1);
        unsigned dst = rb + s * 1024u;
        asm volatile("cp.async.cg.shared.global [%0], [%1], 16;"
                     :: "r"(dst), "l"(kp + (size_t)jc * rs) : "memory");
        asm volatile("cp.async.cg.shared.global [%0], [%1], 16;"
                     :: "r"(dst + 512u), "l"(vp + (size_t)jc * rs) : "memory");
        asm volatile("cp.async.commit_group;" ::: "memory");
    }

    int j = j0;
    int it = 0;
    while (j < ctx) {
        asm volatile("cp.async.wait_group 2;" ::: "memory");
        const int cur = it & 3;
        float4 kv = ring[wid][cur][lane];
        float4 vv = ring[wid][cur][32 + lane];

        // refill the slot 3 stages ahead (reuses the slot freed last iteration)
        {
            int jc = min(j + 192, ctx - 1);
            unsigned dst = rb + ((unsigned)((it + 3) & 3)) * 1024u;
            asm volatile("cp.async.cg.shared.global [%0], [%1], 16;"
                         :: "r"(dst), "l"(kp + (size_t)jc * rs) : "memory");
            asm volatile("cp.async.cg.shared.global [%0], [%1], 16;"
                         :: "r"(dst + 512u), "l"(vp + (size_t)jc * rs) : "memory");
            asm volatile("cp.async.commit_group;" ::: "memory");
        }

        float sv[4];
        #pragma unroll
        for (int g = 0; g < 4; g++)
            sv[g] = fmaf(q[g].x, kv.x, fmaf(q[g].y, kv.y,
                     fmaf(q[g].z, kv.z, q[g].w * kv.w)));
        #pragma unroll
        for (int off = 16; off > 0; off >>= 1) {
            sv[0] += __shfl_xor_sync(0xffffffffu, sv[0], off);
            sv[1] += __shfl_xor_sync(0xffffffffu, sv[1], off);
            sv[2] += __shfl_xor_sync(0xffffffffu, sv[2], off);
            sv[3] += __shfl_xor_sync(0xffffffffu, sv[3], off);
        }
        #pragma unroll
        for (int g = 0; g < 4; g++) {
            float p = __expf(sv[g] - M_FIX);
            l[g] += p;
            acc[g].x = fmaf(p, vv.x, acc[g].x);
            acc[g].y = fmaf(p, vv.y, acc[g].y);
            acc[g].z = fmaf(p, vv.z, acc[g].z);
            acc[g].w = fmaf(p, vv.w, acc[g].w);
        }
        j += 64;
        it++;
    }

    if (lane == 0) {
        #pragma unroll
        for (int g = 0; g < 4; g++) sl[wid][g] = l[g];
    }
    #pragma unroll
    for (int g = 0; g < 4; g++)
        *(float4*)(&sacc[wid][g][lane * 4]) = acc[g];
    __syncthreads();

    // combine the 4 warps: plain sums (common fixed shift cancels later)
    const int g = tid >> 5;
    const int l32 = tid & 31;
    float L = 0.f;
    float4 V = make_float4(0.f, 0.f, 0.f, 0.f);
    #pragma unroll
    for (int w = 0; w < 4; w++) {
        L += sl[w][g];
        float4 a = *(const float4*)(&sacc[w][g][l32 * 4]);
        V.x += a.x; V.y += a.y; V.z += a.z; V.w += a.w;
    }
    const size_t pb = (size_t)(blk * GRP + g) * DIM;
    *(float4*)&g_pacc[pb + l32 * 4] = V;
    if (l32 == 0) g_pl[blk * GRP + g] = L;
}

// combine NSPLIT partials -> g_attn[b, h, d]. grid = B*KVH*G (1024), block 128.
__global__ void attn_reduce() {
    const int idx = blockIdx.x;
    const int g = idx & 3;
    const int kvh = (idx >> 2) & 7;
    const int b = idx >> 5;
    const int d = threadIdx.x;
    const int base = ((b * KVHEADS + kvh) * NSPLIT) * GRP + g;
    float L = 0.f, a = 0.f;
    #pragma unroll
    for (int s = 0; s < NSPLIT; s++) {
        L += g_pl[base + s * GRP];
        a += g_pacc[(size_t)(base + s * GRP) * DIM + d];
    }
    g_attn[((size_t)(b * HEADS + kvh * GRP + g) << 7) + d] = a / L;
}

// ------------------------------ launch --------------------------------------
extern "C" void kernel_launch(void* const* d_in, const int* in_sizes, int n_in,
                              void* d_out, int out_size) {
    const float* hs = (const float*)d_in[0];
    const int* pos = (const int*)d_in[1];
    const float* kc = (const float*)d_in[2];
    const float* vc = (const float*)d_in[3];
    const int* cl = (const int*)d_in[4];
    const float* wq = (const float*)d_in[5];
    const float* wo = (const float*)d_in[6];
    float* out = (float*)d_out;

    float* qbuf = nullptr;
    float* abuf = nullptr;
    cudaGetSymbolAddress((void**)&qbuf, g_q);
    cudaGetSymbolAddress((void**)&abuf, g_attn);

    // q = hs @ wq.T
    gemm_tn<<<dim3(16, KSG), 256>>>(hs, wq);
    ksum_part<<<512, 256>>>(qbuf);
    // RoPE in place
    rope_kernel<<<1024, 64>>>(pos);
    // flash-decode attention, strided split over K
    attn_kernel<<<BATCH * KVHEADS * NSPLIT, 128>>>(kc, vc, cl);
    attn_reduce<<<BATCH * KVHEADS * GRP, 128>>>();
    // out = attn @ wo.T
    gemm_tn<<<dim3(16, KSG), 256>>>(abuf, wo);
    ksum_part<<<512, 256>>>(out);
}

// round 8
// speedup vs baseline: 1.5018x; 1.0236x over previous
#include <cuda_runtime.h>
#include <cstdint>
#include <math.h>

#define BATCH 32
#define HEADS 32
#define KVHEADS 8
#define DIM 128
#define KCTX 4096
#define HSZ 4096
#define GRP 4
#define NSPLIT 16
#define KSG 16                     // gemm k-splits
#define QK_SCALE 0.08838834764831845f
#define M_FIX 16.0f                // fixed softmax shift (scale-invariant)

// ------------------------------ scratch (no allocs allowed) ------------------
__device__ float g_q[BATCH * HSZ];                              // 512 KB
__device__ float g_attn[BATCH * HSZ];                           // 512 KB
__device__ float g_gpart[KSG * BATCH * HSZ];                    // 8 MB (gemm split-K partials)
__device__ float g_pacc[BATCH * KVHEADS * NSPLIT * GRP * DIM];  // 8 MB (attn partials)
__device__ float g_pl[BATCH * KVHEADS * NSPLIT * GRP];

// ------------------------------ helpers -------------------------------------
__device__ __forceinline__ unsigned f2tf(float x) {
    unsigned r;
    asm("cvt.rna.tf32.f32 %0, %1;" : "=r"(r) : "f"(x));
    return r;
}

__device__ __forceinline__ void cpasync16(void* smem_dst, const void* gsrc) {
    unsigned d = (unsigned)__cvta_generic_to_shared(smem_dst);
    asm volatile("cp.async.cg.shared.global [%0], [%1], 16;"
                 :: "r"(d), "l"(gsrc) : "memory");
}

#define MMA4(C, A0, A1, B0)                                                    \
    asm volatile(                                                              \
        "mma.sync.aligned.m16n8k4.row.col.f32.tf32.tf32.f32 "                  \
        "{%0,%1,%2,%3},{%4,%5},{%6},{%0,%1,%2,%3};"                            \
        : "+f"((C)[0]), "+f"((C)[1]), "+f"((C)[2]), "+f"((C)[3])               \
        : "r"(A0), "r"(A1), "r"(B0))

// ------------------------------ GEMM (3xTF32 tensor): out[b,n]=sum A[b,k]W[n,k]
// M=32, N=4096, K=4096. Grid (32 n-tiles of 128, KSG=16 k-splits), 256 thr.
// 8 warps = 2 m16-halves x 4 n32-groups. Each warp: m16 x n32 (4 n8 tiles).
// Split x = hi + lo in tf32; D = Ah*Bh + Al*Bh + Ah*Bl (fp32 accum) ~ fp32.
__global__ __launch_bounds__(256) void gemm_tf32(const float* __restrict__ A,
                                                 const float* __restrict__ W) {
    __shared__ float As[2][32][36];    // 9.2 KB  (stride 36 == 4 mod 32)
    __shared__ float Ws[2][128][36];   // 36.9 KB
    const int tid = threadIdx.x;
    const int warp = tid >> 5;
    const int lane = tid & 31;
    const int groupID = lane >> 2;
    const int tig = lane & 3;
    const int mh = warp & 1;           // m16 half
    const int ng = warp >> 1;          // n32 group (0..3)
    const int n0 = blockIdx.x * 128;
    const int ks = blockIdx.y;
    const int kbeg = ks * (HSZ / KSG); // 256-wide k chunk, 8 stages of 32

    float c[4][4] = {};                // 4 n8-tiles x (c0..c3)

#define LOAD_STAGE(s, kb)                                                      \
    do {                                                                       \
        int ar_ = tid >> 3, ak_ = (tid & 7) * 4;                               \
        cpasync16(&As[s][ar_][ak_], A + (size_t)ar_ * HSZ + (kb) + ak_);       \
        _Pragma("unroll")                                                      \
        for (int r_ = 0; r_ < 4; r_++) {                                       \
            int idx_ = tid + 256 * r_;                                         \
            int wr_ = idx_ >> 3, wk_ = (idx_ & 7) * 4;                         \
            cpasync16(&Ws[s][wr_][wk_],                                        \
                      W + (size_t)(n0 + wr_) * HSZ + (kb) + wk_);              \
        }                                                                      \
        asm volatile("cp.async.commit_group;" ::: "memory");                   \
    } while (0)

    LOAD_STAGE(0, kbeg);
    #pragma unroll 1
    for (int i = 0; i < 8; i++) {
        const int s = i & 1;
        if (i < 7) {
            LOAD_STAGE(s ^ 1, kbeg + (i + 1) * 32);
            asm volatile("cp.async.wait_group 1;" ::: "memory");
        } else {
            asm volatile("cp.async.wait_group 0;" ::: "memory");
        }
        __syncthreads();

        #pragma unroll
        for (int k4 = 0; k4 < 8; k4++) {
            const int k = k4 * 4 + tig;
            float a0f = As[s][mh * 16 + groupID][k];
            float a1f = As[s][mh * 16 + groupID + 8][k];
            unsigned a0h = f2tf(a0f), a1h = f2tf(a1f);
            unsigned a0l = f2tf(a0f - __uint_as_float(a0h));
            unsigned a1l = f2tf(a1f - __uint_as_float(a1h));
            #pragma unroll
            for (int nt = 0; nt < 4; nt++) {
                float bf = Ws[s][ng * 32 + nt * 8 + groupID][k];
                unsigned bh = f2tf(bf);
                unsigned bl = f2tf(bf - __uint_as_float(bh));
                MMA4(c[nt], a0h, a1h, bh);
                MMA4(c[nt], a0l, a1l, bh);
                MMA4(c[nt], a0h, a1h, bl);
            }
        }
        __syncthreads();
    }
#undef LOAD_STAGE

    float* outp = g_gpart + (size_t)ks * (BATCH * HSZ);
    const int m = mh * 16 + groupID;
    #pragma unroll
    for (int nt = 0; nt < 4; nt++) {
        int n = n0 + ng * 32 + nt * 8 + 2 * tig;
        *(float2*)&outp[(size_t)m * HSZ + n] = make_float2(c[nt][0], c[nt][1]);
        *(float2*)&outp[(size_t)(m + 8) * HSZ + n] = make_float2(c[nt][2], c[nt][3]);
    }
}

// sum the KSG split-K partials into dst. 131072 elems.
__global__ void ksum_part(float* __restrict__ dst) {
    int i = blockIdx.x * blockDim.x + threadIdx.x;
    float s = 0.f;
    #pragma unroll
    for (int p = 0; p < KSG; p++) s += g_gpart[(size_t)p * (BATCH * HSZ) + i];
    dst[i] = s;
}

// ------------------------------ RoPE (in-place on g_q) ----------------------
__global__ void rope_kernel(const int* __restrict__ positions) {
    const int bh = blockIdx.x;
    const int b = bh >> 5;
    const int j = threadIdx.x;           // 0..63
    double inv = exp(-(double)j * (13.815510557964274 / 64.0));
    double ang = (double)positions[b] * inv;
    double sd, cd;
    sincos(ang, &sd, &cd);
    float c = (float)cd, s = (float)sd;
    float* qp = g_q + ((size_t)bh << 7);
    float q1 = qp[j], q2 = qp[j + 64];
    qp[j]      = q1 * c - q2 * s;
    qp[j + 64] = q2 * c + q1 * s;
}

// ------------------------------ attention ----------------------------------
// grid = B*KVH*NSPLIT (4096), block 128 (4 warps). Full warp per key.
// cp.async depth-4 smem ring per warp. q in registers. Fixed-shift softmax.
__global__ __launch_bounds__(128, 8) void attn_kernel(const float* __restrict__ kc,
                                                      const float* __restrict__ vc,
                                                      const int* __restrict__ clens) {
    const int blk = blockIdx.x;
    const int split = blk & 15;
    const int kvh = (blk >> 4) & 7;
    const int b = blk >> 7;
    const int tid = threadIdx.x;
    const int wid = tid >> 5;
    const int lane = tid & 31;

    __shared__ float4 ring[4][4][64];   // [warp][stage][K:0-31 | V:32-63]  16 KB
    __shared__ float sl[4][GRP];
    __shared__ float sacc[4][GRP][DIM]; // 8 KB

    float4 q[GRP];
    {
        const float* qg = g_q + ((size_t)(b * HEADS + kvh * GRP) << 7) + lane * 4;
        #pragma unroll
        for (int g = 0; g < GRP; g++) {
            float4 t = *(const float4*)(qg + g * DIM);
            q[g].x = t.x * QK_SCALE; q[g].y = t.y * QK_SCALE;
            q[g].z = t.z * QK_SCALE; q[g].w = t.w * QK_SCALE;
        }
    }

    const int ctx = clens[b];
    const size_t rs = (size_t)KVHEADS * DIM; // 1024 floats per key index
    const float* kp = kc + (size_t)b * KCTX * rs + (size_t)kvh * DIM + lane * 4;
    const float* vp = vc + (size_t)b * KCTX * rs + (size_t)kvh * DIM + lane * 4;

    float l[4] = {0.f, 0.f, 0.f, 0.f};
    float4 acc[4];
    #pragma unroll
    for (int g = 0; g < 4; g++) acc[g] = make_float4(0.f, 0.f, 0.f, 0.f);

    const unsigned rb =
        (unsigned)__cvta_generic_to_shared(&ring[wid][0][0]) + lane * 16u;

    const int j0 = split + 16 * wid;   // this warp's first key; stride 64

    #pragma unroll
    for (int s = 0; s < 3; s++) {
        int jc = min(j0 + 64 * s, ctx - 1);
        unsigned dst = rb + s * 1024u;
        asm volatile("cp.async.cg.shared.global [%0], [%1], 16;"
                     :: "r"(dst), "l"(kp + (size_t)jc * rs) : "memory");
        asm volatile("cp.async.cg.shared.global [%0], [%1], 16;"
                     :: "r"(dst + 512u), "l"(vp + (size_t)jc * rs) : "memory");
        asm volatile("cp.async.commit_group;" ::: "memory");
    }

    int j = j0;
    int it = 0;
    while (j < ctx) {
        asm volatile("cp.async.wait_group 2;" ::: "memory");
        const int cur = it & 3;
        float4 kv = ring[wid][cur][lane];
        float4 vv = ring[wid][cur][32 + lane];

        {
            int jc = min(j + 192, ctx - 1);
            unsigned dst = rb + ((unsigned)((it + 3) & 3)) * 1024u;
            asm volatile("cp.async.cg.shared.global [%0], [%1], 16;"
                         :: "r"(dst), "l"(kp + (size_t)jc * rs) : "memory");
            asm volatile("cp.async.cg.shared.global [%0], [%1], 16;"
                         :: "r"(dst + 512u), "l"(vp + (size_t)jc * rs) : "memory");
            asm volatile("cp.async.commit_group;" ::: "memory");
        }

        float sv[4];
        #pragma unroll
        for (int g = 0; g < 4; g++)
            sv[g] = fmaf(q[g].x, kv.x, fmaf(q[g].y, kv.y,
                     fmaf(q[g].z, kv.z, q[g].w * kv.w)));
        #pragma unroll
        for (int off = 16; off > 0; off >>= 1) {
            sv[0] += __shfl_xor_sync(0xffffffffu, sv[0], off);
            sv[1] += __shfl_xor_sync(0xffffffffu, sv[1], off);
            sv[2] += __shfl_xor_sync(0xffffffffu, sv[2], off);
            sv[3] += __shfl_xor_sync(0xffffffffu, sv[3], off);
        }
        #pragma unroll
        for (int g = 0; g < 4; g++) {
            float p = __expf(sv[g] - M_FIX);
            l[g] += p;
            acc[g].x = fmaf(p, vv.x, acc[g].x);
            acc[g].y = fmaf(p, vv.y, acc[g].y);
            acc[g].z = fmaf(p, vv.z, acc[g].z);
            acc[g].w = fmaf(p, vv.w, acc[g].w);
        }
        j += 64;
        it++;
    }

    if (lane == 0) {
        #pragma unroll
        for (int g = 0; g < 4; g++) sl[wid][g] = l[g];
    }
    #pragma unroll
    for (int g = 0; g < 4; g++)
        *(float4*)(&sacc[wid][g][lane * 4]) = acc[g];
    __syncthreads();

    const int g = tid >> 5;
    const int l32 = tid & 31;
    float L = 0.f;
    float4 V = make_float4(0.f, 0.f, 0.f, 0.f);
    #pragma unroll
    for (int w = 0; w < 4; w++) {
        L += sl[w][g];
        float4 a = *(const float4*)(&sacc[w][g][l32 * 4]);
        V.x += a.x; V.y += a.y; V.z += a.z; V.w += a.w;
    }
    const size_t pb = (size_t)(blk * GRP + g) * DIM;
    *(float4*)&g_pacc[pb + l32 * 4] = V;
    if (l32 == 0) g_pl[blk * GRP + g] = L;
}

// combine NSPLIT partials -> g_attn[b, h, d]. grid = B*KVH*G (1024), block 128.
__global__ void attn_reduce() {
    const int idx = blockIdx.x;
    const int g = idx & 3;
    const int kvh = (idx >> 2) & 7;
    const int b = idx >> 5;
    const int d = threadIdx.x;
    const int base = ((b * KVHEADS + kvh) * NSPLIT) * GRP + g;
    float L = 0.f, a = 0.f;
    #pragma unroll
    for (int s = 0; s < NSPLIT; s++) {
        L += g_pl[base + s * GRP];
        a += g_pacc[(size_t)(base + s * GRP) * DIM + d];
    }
    g_attn[((size_t)(b * HEADS + kvh * GRP + g) << 7) + d] = a / L;
}

// ------------------------------ launch --------------------------------------
extern "C" void kernel_launch(void* const* d_in, const int* in_sizes, int n_in,
                              void* d_out, int out_size) {
    const float* hs = (const float*)d_in[0];
    const int* pos = (const int*)d_in[1];
    const float* kc = (const float*)d_in[2];
    const float* vc = (const float*)d_in[3];
    const int* cl = (const int*)d_in[4];
    const float* wq = (const float*)d_in[5];
    const float* wo = (const float*)d_in[6];
    float* out = (float*)d_out;

    float* qbuf = nullptr;
    float* abuf = nullptr;
    cudaGetSymbolAddress((void**)&qbuf, g_q);
    cudaGetSymbolAddress((void**)&abuf, g_attn);

    // q = hs @ wq.T   (3xTF32 tensor-core GEMM, split-K)
    gemm_tf32<<<dim3(32, KSG), 256>>>(hs, wq);
    ksum_part<<<512, 256>>>(qbuf);
    // RoPE in place
    rope_kernel<<<1024, 64>>>(pos);
    // flash-decode attention, strided split over K
    attn_kernel<<<BATCH * KVHEADS * NSPLIT, 128>>>(kc, vc, cl);
    attn_reduce<<<BATCH * KVHEADS * GRP, 128>>>();
    // out = attn @ wo.T
    gemm_tf32<<<dim3(32, KSG), 256>>>(abuf, wo);
    ksum_part<<<512, 256>>>(out);
}

// round 9
// speedup vs baseline: 1.6718x; 1.1132x over previous
#include <cuda_runtime.h>
#include <cstdint>
#include <math.h>

#define BATCH 32
#define HEADS 32
#define KVHEADS 8
#define DIM 128
#define KCTX 4096
#define HSZ 4096
#define GRP 4
#define NSPLIT 16
#define KSG 16                     // gemm k-splits
#define QK_SCALE 0.08838834764831845f
#define M_FIX 16.0f                // fixed softmax shift (scale-invariant)

// ------------------------------ scratch (no allocs allowed) ------------------
__device__ float g_q[BATCH * HSZ];                              // 512 KB
__device__ float g_attn[BATCH * HSZ];                           // 512 KB
__device__ float g_gpart[KSG * BATCH * HSZ];                    // 8 MB (gemm split-K partials)
__device__ float g_pacc[BATCH * KVHEADS * NSPLIT * GRP * DIM];  // 8 MB (attn partials)
__device__ float g_pl[BATCH * KVHEADS * NSPLIT * GRP];

// ------------------------------ helpers -------------------------------------
__device__ __forceinline__ unsigned f2tf(float x) {
    unsigned r;
    asm("cvt.rna.tf32.f32 %0, %1;" : "=r"(r) : "f"(x));
    return r;
}

__device__ __forceinline__ void cpasync16(void* smem_dst, const void* gsrc) {
    unsigned d = (unsigned)__cvta_generic_to_shared(smem_dst);
    asm volatile("cp.async.cg.shared.global [%0], [%1], 16;"
                 :: "r"(d), "l"(gsrc) : "memory");
}

#define MMA4(C, A0, A1, B0)                                                    \
    asm volatile(                                                              \
        "mma.sync.aligned.m16n8k4.row.col.f32.tf32.tf32.f32 "                  \
        "{%0,%1,%2,%3},{%4,%5},{%6},{%0,%1,%2,%3};"                            \
        : "+f"((C)[0]), "+f"((C)[1]), "+f"((C)[2]), "+f"((C)[3])               \
        : "r"(A0), "r"(A1), "r"(B0))

#define GEMM_LOAD_STAGE(s, kb)                                                 \
    do {                                                                       \
        int ar_ = tid >> 3, ak_ = (tid & 7) * 4;                               \
        cpasync16(&As[s][ar_][ak_], A + (size_t)ar_ * HSZ + (kb) + ak_);       \
        _Pragma("unroll")                                                      \
        for (int r_ = 0; r_ < 4; r_++) {                                       \
            int idx_ = tid + 256 * r_;                                         \
            int wr_ = idx_ >> 3, wk_ = (idx_ & 7) * 4;                         \
            cpasync16(&Ws[s][wr_][wk_],                                        \
                      W + (size_t)(n0 + wr_) * HSZ + (kb) + wk_);              \
        }                                                                      \
        asm volatile("cp.async.commit_group;" ::: "memory");                   \
    } while (0)

// ------------------------------ GEMM (3xTF32, fp32-accurate) -----------------
// out[b,n] = sum_k A[b,k] * W[n,k]. M=32, N=4096, K=4096.
// Grid (32 n-tiles of 128, KSG=16 k-splits), 256 thr.
// D = Ah*Bh + Al*Bh + Ah*Bl (fp32 accum) ~ fp32 accuracy. Used for wq
// (softmax-critical: query error is exponentially amplified in scores).
__global__ __launch_bounds__(256) void gemm_tf32(const float* __restrict__ A,
                                                 const float* __restrict__ W) {
    __shared__ float As[2][32][36];
    __shared__ float Ws[2][128][36];
    const int tid = threadIdx.x;
    const int warp = tid >> 5;
    const int lane = tid & 31;
    const int groupID = lane >> 2;
    const int tig = lane & 3;
    const int mh = warp & 1;
    const int ng = warp >> 1;
    const int n0 = blockIdx.x * 128;
    const int ks = blockIdx.y;
    const int kbeg = ks * (HSZ / KSG);

    float c[4][4] = {};

    GEMM_LOAD_STAGE(0, kbeg);
    #pragma unroll 1
    for (int i = 0; i < 8; i++) {
        const int s = i & 1;
        if (i < 7) {
            GEMM_LOAD_STAGE(s ^ 1, kbeg + (i + 1) * 32);
            asm volatile("cp.async.wait_group 1;" ::: "memory");
        } else {
            asm volatile("cp.async.wait_group 0;" ::: "memory");
        }
        __syncthreads();

        #pragma unroll
        for (int k4 = 0; k4 < 8; k4++) {
            const int k = k4 * 4 + tig;
            float a0f = As[s][mh * 16 + groupID][k];
            float a1f = As[s][mh * 16 + groupID + 8][k];
            unsigned a0h = f2tf(a0f), a1h = f2tf(a1f);
            unsigned a0l = f2tf(a0f - __uint_as_float(a0h));
            unsigned a1l = f2tf(a1f - __uint_as_float(a1h));
            #pragma unroll
            for (int nt = 0; nt < 4; nt++) {
                float bf = Ws[s][ng * 32 + nt * 8 + groupID][k];
                unsigned bh = f2tf(bf);
                unsigned bl = f2tf(bf - __uint_as_float(bh));
                MMA4(c[nt], a0h, a1h, bh);
                MMA4(c[nt], a0l, a1l, bh);
                MMA4(c[nt], a0h, a1h, bl);
            }
        }
        __syncthreads();
    }

    float* outp = g_gpart + (size_t)ks * (BATCH * HSZ);
    const int m = mh * 16 + groupID;
    #pragma unroll
    for (int nt = 0; nt < 4; nt++) {
        int n = n0 + ng * 32 + nt * 8 + 2 * tig;
        *(float2*)&outp[(size_t)m * HSZ + n] = make_float2(c[nt][0], c[nt][1]);
        *(float2*)&outp[(size_t)(m + 8) * HSZ + n] = make_float2(c[nt][2], c[nt][3]);
    }
}

// ------------------------------ GEMM (1xTF32, fast) --------------------------
// Same tiling, single-pass tf32 (rel err ~2e-4). Used for wo only: the final
// projection is a pure linear map, so this error lands directly (unamplified)
// on the output, well inside the 1e-3 budget.
__global__ __launch_bounds__(256) void gemm_tf32_fast(const float* __restrict__ A,
                                                      const float* __restrict__ W) {
    __shared__ float As[2][32][36];
    __shared__ float Ws[2][128][36];
    const int tid = threadIdx.x;
    const int warp = tid >> 5;
    const int lane = tid & 31;
    const int groupID = lane >> 2;
    const int tig = lane & 3;
    const int mh = warp & 1;
    const int ng = warp >> 1;
    const int n0 = blockIdx.x * 128;
    const int ks = blockIdx.y;
    const int kbeg = ks * (HSZ / KSG);

    float c[4][4] = {};

    GEMM_LOAD_STAGE(0, kbeg);
    #pragma unroll 1
    for (int i = 0; i < 8; i++) {
        const int s = i & 1;
        if (i < 7) {
            GEMM_LOAD_STAGE(s ^ 1, kbeg + (i + 1) * 32);
            asm volatile("cp.async.wait_group 1;" ::: "memory");
        } else {
            asm volatile("cp.async.wait_group 0;" ::: "memory");
        }
        __syncthreads();

        #pragma unroll
        for (int k4 = 0; k4 < 8; k4++) {
            const int k = k4 * 4 + tig;
            unsigned a0h = f2tf(As[s][mh * 16 + groupID][k]);
            unsigned a1h = f2tf(As[s][mh * 16 + groupID + 8][k]);
            #pragma unroll
            for (int nt = 0; nt < 4; nt++) {
                unsigned bh = f2tf(Ws[s][ng * 32 + nt * 8 + groupID][k]);
                MMA4(c[nt], a0h, a1h, bh);
            }
        }
        __syncthreads();
    }

    float* outp = g_gpart + (size_t)ks * (BATCH * HSZ);
    const int m = mh * 16 + groupID;
    #pragma unroll
    for (int nt = 0; nt < 4; nt++) {
        int n = n0 + ng * 32 + nt * 8 + 2 * tig;
        *(float2*)&outp[(size_t)m * HSZ + n] = make_float2(c[nt][0], c[nt][1]);
        *(float2*)&outp[(size_t)(m + 8) * HSZ + n] = make_float2(c[nt][2], c[nt][3]);
    }
}

// sum the KSG split-K partials into dst. 131072 elems.
__global__ void ksum_part(float* __restrict__ dst) {
    int i = blockIdx.x * blockDim.x + threadIdx.x;
    float s = 0.f;
    #pragma unroll
    for (int p = 0; p < KSG; p++) s += g_gpart[(size_t)p * (BATCH * HSZ) + i];
    dst[i] = s;
}

// ------------------------------ RoPE (in-place on g_q) ----------------------
__global__ void rope_kernel(const int* __restrict__ positions) {
    const int bh = blockIdx.x;
    const int b = bh >> 5;
    const int j = threadIdx.x;           // 0..63
    double inv = exp(-(double)j * (13.815510557964274 / 64.0));
    double ang = (double)positions[b] * inv;
    double sd, cd;
    sincos(ang, &sd, &cd);
    float c = (float)cd, s = (float)sd;
    float* qp = g_q + ((size_t)bh << 7);
    float q1 = qp[j], q2 = qp[j + 64];
    qp[j]      = q1 * c - q2 * s;
    qp[j + 64] = q2 * c + q1 * s;
}

// ------------------------------ attention ----------------------------------
// grid = B*KVH*NSPLIT (4096), block 128 (4 warps). Full warp per key.
// cp.async depth-4 smem ring per warp. q in registers. Fixed-shift softmax.
__global__ __launch_bounds__(128, 8) void attn_kernel(const float* __restrict__ kc,
                                                      const float* __restrict__ vc,
                                                      const int* __restrict__ clens) {
    const int blk = blockIdx.x;
    const int split = blk & 15;
    const int kvh = (blk >> 4) & 7;
    const int b = blk >> 7;
    const int tid = threadIdx.x;
    const int wid = tid >> 5;
    const int lane = tid & 31;

    __shared__ float4 ring[4][4][64];   // [warp][stage][K:0-31 | V:32-63]  16 KB
    __shared__ float sl[4][GRP];
    __shared__ float sacc[4][GRP][DIM]; // 8 KB

    float4 q[GRP];
    {
        const float* qg = g_q + ((size_t)(b * HEADS + kvh * GRP) << 7) + lane * 4;
        #pragma unroll
        for (int g = 0; g < GRP; g++) {
            float4 t = *(const float4*)(qg + g * DIM);
            q[g].x = t.x * QK_SCALE; q[g].y = t.y * QK_SCALE;
            q[g].z = t.z * QK_SCALE; q[g].w = t.w * QK_SCALE;
        }
    }

    const int ctx = clens[b];
    const size_t rs = (size_t)KVHEADS * DIM; // 1024 floats per key index
    const float* kp = kc + (size_t)b * KCTX * rs + (size_t)kvh * DIM + lane * 4;
    const float* vp = vc + (size_t)b * KCTX * rs + (size_t)kvh * DIM + lane * 4;

    float l[4] = {0.f, 0.f, 0.f, 0.f};
    float4 acc[4];
    #pragma unroll
    for (int g = 0; g < 4; g++) acc[g] = make_float4(0.f, 0.f, 0.f, 0.f);

    const unsigned rb =
        (unsigned)__cvta_generic_to_shared(&ring[wid][0][0]) + lane * 16u;

    const int j0 = split + 16 * wid;   // this warp's first key; stride 64

    #pragma unroll
    for (int s = 0; s < 3; s++) {
        int jc = min(j0 + 64 * s, ctx - 1);
        unsigned dst = rb + s * 1024u;
        asm volatile("cp.async.cg.shared.global [%0], [%1], 16;"
                     :: "r"(dst), "l"(kp + (size_t)jc * rs) : "memory");
        asm volatile("cp.async.cg.shared.global [%0], [%1], 16;"
                     :: "r"(dst + 512u), "l"(vp + (size_t)jc * rs) : "memory");
        asm volatile("cp.async.commit_group;" ::: "memory");
    }

    int j = j0;
    int it = 0;
    while (j < ctx) {
        asm volatile("cp.async.wait_group 2;" ::: "memory");
        const int cur = it & 3;
        float4 kv = ring[wid][cur][lane];
        float4 vv = ring[wid][cur][32 + lane];

        {
            int jc = min(j + 192, ctx - 1);
            unsigned dst = rb + ((unsigned)((it + 3) & 3)) * 1024u;
            asm volatile("cp.async.cg.shared.global [%0], [%1], 16;"
                         :: "r"(dst), "l"(kp + (size_t)jc * rs) : "memory");
            asm volatile("cp.async.cg.shared.global [%0], [%1], 16;"
                         :: "r"(dst + 512u), "l"(vp + (size_t)jc * rs) : "memory");
            asm volatile("cp.async.commit_group;" ::: "memory");
        }

        float sv[4];
        #pragma unroll
        for (int g = 0; g < 4; g++)
            sv[g] = fmaf(q[g].x, kv.x, fmaf(q[g].y, kv.y,
                     fmaf(q[g].z, kv.z, q[g].w * kv.w)));
        #pragma unroll
        for (int off = 16; off > 0; off >>= 1) {
            sv[0] += __shfl_xor_sync(0xffffffffu, sv[0], off);
            sv[1] += __shfl_xor_sync(0xffffffffu, sv[1], off);
            sv[2] += __shfl_xor_sync(0xffffffffu, sv[2], off);
            sv[3] += __shfl_xor_sync(0xffffffffu, sv[3], off);
        }
        #pragma unroll
        for (int g = 0; g < 4; g++) {
            float p = __expf(sv[g] - M_FIX);
            l[g] += p;
            acc[g].x = fmaf(p, vv.x, acc[g].x);
            acc[g].y = fmaf(p, vv.y, acc[g].y);
            acc[g].z = fmaf(p, vv.z, acc[g].z);
            acc[g].w = fmaf(p, vv.w, acc[g].w);
        }
        j += 64;
        it++;
    }

    if (lane == 0) {
        #pragma unroll
        for (int g = 0; g < 4; g++) sl[wid][g] = l[g];
    }
    #pragma unroll
    for (int g = 0; g < 4; g++)
        *(float4*)(&sacc[wid][g][lane * 4]) = acc[g];
    __syncthreads();

    const int g = tid >> 5;
    const int l32 = tid & 31;
    float L = 0.f;
    float4 V = make_float4(0.f, 0.f, 0.f, 0.f);
    #pragma unroll
    for (int w = 0; w < 4; w++) {
        L += sl[w][g];
        float4 a = *(const float4*)(&sacc[w][g][l32 * 4]);
        V.x += a.x; V.y += a.y; V.z += a.z; V.w += a.w;
    }
    const size_t pb = (size_t)(blk * GRP + g) * DIM;
    *(float4*)&g_pacc[pb + l32 * 4] = V;
    if (l32 == 0) g_pl[blk * GRP + g] = L;
}

// combine NSPLIT partials -> g_attn[b, h, d]. grid = B*KVH*G (1024), block 128.
__global__ void attn_reduce() {
    const int idx = blockIdx.x;
    const int g = idx & 3;
    const int kvh = (idx >> 2) & 7;
    const int b = idx >> 5;
    const int d = threadIdx.x;
    const int base = ((b * KVHEADS + kvh) * NSPLIT) * GRP + g;
    float L = 0.f, a = 0.f;
    #pragma unroll
    for (int s = 0; s < NSPLIT; s++) {
        L += g_pl[base + s * GRP];
        a += g_pacc[(size_t)(base + s * GRP) * DIM + d];
    }
    g_attn[((size_t)(b * HEADS + kvh * GRP + g) << 7) + d] = a / L;
}

// ------------------------------ launch --------------------------------------
extern "C" void kernel_launch(void* const* d_in, const int* in_sizes, int n_in,
                              void* d_out, int out_size) {
    const float* hs = (const float*)d_in[0];
    const int* pos = (const int*)d_in[1];
    const float* kc = (const float*)d_in[2];
    const float* vc = (const float*)d_in[3];
    const int* cl = (const int*)d_in[4];
    const float* wq = (const float*)d_in[5];
    const float* wo = (const float*)d_in[6];
    float* out = (float*)d_out;

    float* qbuf = nullptr;
    float* abuf = nullptr;
    cudaGetSymbolAddress((void**)&qbuf, g_q);
    cudaGetSymbolAddress((void**)&abuf, g_attn);

    // q = hs @ wq.T   (3xTF32: fp32-accurate, softmax-critical)
    gemm_tf32<<<dim3(32, KSG), 256>>>(hs, wq);
    ksum_part<<<512, 256>>>(qbuf);
    // RoPE in place
    rope_kernel<<<1024, 64>>>(pos);
    // flash-decode attention, strided split over K
    attn_kernel<<<BATCH * KVHEADS * NSPLIT, 128>>>(kc, vc, cl);
    attn_reduce<<<BATCH * KVHEADS * GRP, 128>>>();
    // out = attn @ wo.T  (1xTF32: linear on output, error unamplified)
    gemm_tf32_fast<<<dim3(32, KSG), 256>>>(abuf, wo);
    ksum_part<<<512, 256>>>(out);
}

// round 10
// speedup vs baseline: 1.6849x; 1.0079x over previous
#include <cuda_runtime.h>
#include <cstdint>
#include <math.h>

#define BATCH 32
#define HEADS 32
#define KVHEADS 8
#define DIM 128
#define KCTX 4096
#define HSZ 4096
#define GRP 4
#define NSPLIT 16
#define KSG 16                     // gemm k-splits
#define QK_SCALE 0.08838834764831845f
#define M_FIX 16.0f                // fixed softmax shift (scale-invariant)

// ------------------------------ scratch (no allocs allowed) ------------------
__device__ float g_q[BATCH * HSZ];                              // 512 KB
__device__ float g_attn[BATCH * HSZ];                           // 512 KB
__device__ float g_gpart[KSG * BATCH * HSZ];                    // 8 MB (gemm split-K partials)
__device__ float g_pacc[BATCH * KVHEADS * NSPLIT * GRP * DIM];  // 8 MB (attn partials)
__device__ float g_pl[BATCH * KVHEADS * NSPLIT * GRP];

// ------------------------------ helpers -------------------------------------
__device__ __forceinline__ unsigned f2tf(float x) {
    unsigned r;
    asm("cvt.rna.tf32.f32 %0, %1;" : "=r"(r) : "f"(x));
    return r;
}

__device__ __forceinline__ void cpasync16(void* smem_dst, const void* gsrc) {
    unsigned d = (unsigned)__cvta_generic_to_shared(smem_dst);
    asm volatile("cp.async.cg.shared.global [%0], [%1], 16;"
                 :: "r"(d), "l"(gsrc) : "memory");
}

#define MMA4(C, A0, A1, B0)                                                    \
    asm volatile(                                                              \
        "mma.sync.aligned.m16n8k4.row.col.f32.tf32.tf32.f32 "                  \
        "{%0,%1,%2,%3},{%4,%5},{%6},{%0,%1,%2,%3};"                            \
        : "+f"((C)[0]), "+f"((C)[1]), "+f"((C)[2]), "+f"((C)[3])               \
        : "r"(A0), "r"(A1), "r"(B0))

#define GEMM_LOAD_STAGE(s, kb)                                                 \
    do {                                                                       \
        int ar_ = tid >> 3, ak_ = (tid & 7) * 4;                               \
        cpasync16(&As[s][ar_][ak_], A + (size_t)ar_ * HSZ + (kb) + ak_);       \
        _Pragma("unroll")                                                      \
        for (int r_ = 0; r_ < 4; r_++) {                                       \
            int idx_ = tid + 256 * r_;                                         \
            int wr_ = idx_ >> 3, wk_ = (idx_ & 7) * 4;                         \
            cpasync16(&Ws[s][wr_][wk_],                                        \
                      W + (size_t)(n0 + wr_) * HSZ + (kb) + wk_);              \
        }                                                                      \
        asm volatile("cp.async.commit_group;" ::: "memory");                   \
    } while (0)

// ------------------------------ GEMM (3xTF32, fp32-accurate) -----------------
// Used for wq (softmax-critical; query error is exponentially amplified).
__global__ __launch_bounds__(256) void gemm_tf32(const float* __restrict__ A,
                                                 const float* __restrict__ W) {
    __shared__ float As[2][32][36];
    __shared__ float Ws[2][128][36];
    const int tid = threadIdx.x;
    const int warp = tid >> 5;
    const int lane = tid & 31;
    const int groupID = lane >> 2;
    const int tig = lane & 3;
    const int mh = warp & 1;
    const int ng = warp >> 1;
    const int n0 = blockIdx.x * 128;
    const int ks = blockIdx.y;
    const int kbeg = ks * (HSZ / KSG);

    float c[4][4] = {};

    GEMM_LOAD_STAGE(0, kbeg);
    #pragma unroll 1
    for (int i = 0; i < 8; i++) {
        const int s = i & 1;
        if (i < 7) {
            GEMM_LOAD_STAGE(s ^ 1, kbeg + (i + 1) * 32);
            asm volatile("cp.async.wait_group 1;" ::: "memory");
        } else {
            asm volatile("cp.async.wait_group 0;" ::: "memory");
        }
        __syncthreads();

        #pragma unroll
        for (int k4 = 0; k4 < 8; k4++) {
            const int k = k4 * 4 + tig;
            float a0f = As[s][mh * 16 + groupID][k];
            float a1f = As[s][mh * 16 + groupID + 8][k];
            unsigned a0h = f2tf(a0f), a1h = f2tf(a1f);
            unsigned a0l = f2tf(a0f - __uint_as_float(a0h));
            unsigned a1l = f2tf(a1f - __uint_as_float(a1h));
            #pragma unroll
            for (int nt = 0; nt < 4; nt++) {
                float bf = Ws[s][ng * 32 + nt * 8 + groupID][k];
                unsigned bh = f2tf(bf);
                unsigned bl = f2tf(bf - __uint_as_float(bh));
                MMA4(c[nt], a0h, a1h, bh);
                MMA4(c[nt], a0l, a1l, bh);
                MMA4(c[nt], a0h, a1h, bl);
            }
        }
        __syncthreads();
    }

    float* outp = g_gpart + (size_t)ks * (BATCH * HSZ);
    const int m = mh * 16 + groupID;
    #pragma unroll
    for (int nt = 0; nt < 4; nt++) {
        int n = n0 + ng * 32 + nt * 8 + 2 * tig;
        *(float2*)&outp[(size_t)m * HSZ + n] = make_float2(c[nt][0], c[nt][1]);
        *(float2*)&outp[(size_t)(m + 8) * HSZ + n] = make_float2(c[nt][2], c[nt][3]);
    }
}

// ------------------------------ GEMM (1xTF32, fast) --------------------------
// Used for wo only (pure linear map; ~2e-4 rel error lands unamplified).
__global__ __launch_bounds__(256) void gemm_tf32_fast(const float* __restrict__ A,
                                                      const float* __restrict__ W) {
    __shared__ float As[2][32][36];
    __shared__ float Ws[2][128][36];
    const int tid = threadIdx.x;
    const int warp = tid >> 5;
    const int lane = tid & 31;
    const int groupID = lane >> 2;
    const int tig = lane & 3;
    const int mh = warp & 1;
    const int ng = warp >> 1;
    const int n0 = blockIdx.x * 128;
    const int ks = blockIdx.y;
    const int kbeg = ks * (HSZ / KSG);

    float c[4][4] = {};

    GEMM_LOAD_STAGE(0, kbeg);
    #pragma unroll 1
    for (int i = 0; i < 8; i++) {
        const int s = i & 1;
        if (i < 7) {
            GEMM_LOAD_STAGE(s ^ 1, kbeg + (i + 1) * 32);
            asm volatile("cp.async.wait_group 1;" ::: "memory");
        } else {
            asm volatile("cp.async.wait_group 0;" ::: "memory");
        }
        __syncthreads();

        #pragma unroll
        for (int k4 = 0; k4 < 8; k4++) {
            const int k = k4 * 4 + tig;
            unsigned a0h = f2tf(As[s][mh * 16 + groupID][k]);
            unsigned a1h = f2tf(As[s][mh * 16 + groupID + 8][k]);
            #pragma unroll
            for (int nt = 0; nt < 4; nt++) {
                unsigned bh = f2tf(Ws[s][ng * 32 + nt * 8 + groupID][k]);
                MMA4(c[nt], a0h, a1h, bh);
            }
        }
        __syncthreads();
    }

    float* outp = g_gpart + (size_t)ks * (BATCH * HSZ);
    const int m = mh * 16 + groupID;
    #pragma unroll
    for (int nt = 0; nt < 4; nt++) {
        int n = n0 + ng * 32 + nt * 8 + 2 * tig;
        *(float2*)&outp[(size_t)m * HSZ + n] = make_float2(c[nt][0], c[nt][1]);
        *(float2*)&outp[(size_t)(m + 8) * HSZ + n] = make_float2(c[nt][2], c[nt][3]);
    }
}

// sum the KSG split-K partials into dst. 131072 elems.
__global__ void ksum_part(float* __restrict__ dst) {
    int i = blockIdx.x * blockDim.x + threadIdx.x;
    float s = 0.f;
    #pragma unroll
    for (int p = 0; p < KSG; p++) s += g_gpart[(size_t)p * (BATCH * HSZ) + i];
    dst[i] = s;
}

// ------------------------------ RoPE (in-place on g_q) ----------------------
__global__ void rope_kernel(const int* __restrict__ positions) {
    const int bh = blockIdx.x;
    const int b = bh >> 5;
    const int j = threadIdx.x;           // 0..63
    double inv = exp(-(double)j * (13.815510557964274 / 64.0));
    double ang = (double)positions[b] * inv;
    double sd, cd;
    sincos(ang, &sd, &cd);
    float c = (float)cd, s = (float)sd;
    float* qp = g_q + ((size_t)bh << 7);
    float q1 = qp[j], q2 = qp[j + 64];
    qp[j]      = q1 * c - q2 * s;
    qp[j + 64] = q2 * c + q1 * s;
}

// ------------------------------ attention ----------------------------------
// grid = B*KVH*NSPLIT (4096), block 128 (4 warps). Full warp per key.
// cp.async depth-4 smem ring per warp. q in registers. Fixed-shift softmax.
// Reduction: 2 butterfly stages on all 4 heads, then each 8-lane group adopts
// one head, 3 more stages within the group, ONE exp per lane, 4 idx-broadcasts.
// Same summation tree as 4 full butterflies -> deterministic, identical math.
__global__ __launch_bounds__(128, 8) void attn_kernel(const float* __restrict__ kc,
                                                      const float* __restrict__ vc,
                                                      const int* __restrict__ clens) {
    const int blk = blockIdx.x;
    const int split = blk & 15;
    const int kvh = (blk >> 4) & 7;
    const int b = blk >> 7;
    const int tid = threadIdx.x;
    const int wid = tid >> 5;
    const int lane = tid & 31;

    __shared__ float4 ring[4][4][64];   // [warp][stage][K:0-31 | V:32-63]  16 KB
    __shared__ float sl[4][GRP];
    __shared__ float sacc[4][GRP][DIM]; // 8 KB

    float4 q[GRP];
    {
        const float* qg = g_q + ((size_t)(b * HEADS + kvh * GRP) << 7) + lane * 4;
        #pragma unroll
        for (int g = 0; g < GRP; g++) {
            float4 t = *(const float4*)(qg + g * DIM);
            q[g].x = t.x * QK_SCALE; q[g].y = t.y * QK_SCALE;
            q[g].z = t.z * QK_SCALE; q[g].w = t.w * QK_SCALE;
        }
    }

    const int ctx = clens[b];
    const size_t rs = (size_t)KVHEADS * DIM; // 1024 floats per key index
    const float* kp = kc + (size_t)b * KCTX * rs + (size_t)kvh * DIM + lane * 4;
    const float* vp = vc + (size_t)b * KCTX * rs + (size_t)kvh * DIM + lane * 4;

    float l[4] = {0.f, 0.f, 0.f, 0.f};
    float4 acc[4];
    #pragma unroll
    for (int g = 0; g < 4; g++) acc[g] = make_float4(0.f, 0.f, 0.f, 0.f);

    const unsigned rb =
        (unsigned)__cvta_generic_to_shared(&ring[wid][0][0]) + lane * 16u;

    const int j0 = split + 16 * wid;   // this warp's first key; stride 64
    const int gsel = lane >> 3;        // which head this 8-lane group reduces
    const int lsub = lane & 7;

    #pragma unroll
    for (int s = 0; s < 3; s++) {
        int jc = min(j0 + 64 * s, ctx - 1);
        unsigned dst = rb + s * 1024u;
        asm volatile("cp.async.cg.shared.global [%0], [%1], 16;"
                     :: "r"(dst), "l"(kp + (size_t)jc * rs) : "memory");
        asm volatile("cp.async.cg.shared.global [%0], [%1], 16;"
                     :: "r"(dst + 512u), "l"(vp + (size_t)jc * rs) : "memory");
        asm volatile("cp.async.commit_group;" ::: "memory");
    }

    int j = j0;
    int it = 0;
    while (j < ctx) {
        asm volatile("cp.async.wait_group 2;" ::: "memory");
        const int cur = it & 3;
        float4 kv = ring[wid][cur][lane];
        float4 vv = ring[wid][cur][32 + lane];

        {
            int jc = min(j + 192, ctx - 1);
            unsigned dst = rb + ((unsigned)((it + 3) & 3)) * 1024u;
            asm volatile("cp.async.cg.shared.global [%0], [%1], 16;"
                         :: "r"(dst), "l"(kp + (size_t)jc * rs) : "memory");
            asm volatile("cp.async.cg.shared.global [%0], [%1], 16;"
                         :: "r"(dst + 512u), "l"(vp + (size_t)jc * rs) : "memory");
            asm volatile("cp.async.commit_group;" ::: "memory");
        }

        float sv[4];
        #pragma unroll
        for (int g = 0; g < 4; g++)
            sv[g] = fmaf(q[g].x, kv.x, fmaf(q[g].y, kv.y,
                     fmaf(q[g].z, kv.z, q[g].w * kv.w)));

        // stage A: reduce across xor-16, xor-8 for all 4 heads
        #pragma unroll
        for (int off = 16; off >= 8; off >>= 1) {
            sv[0] += __shfl_xor_sync(0xffffffffu, sv[0], off);
            sv[1] += __shfl_xor_sync(0xffffffffu, sv[1], off);
            sv[2] += __shfl_xor_sync(0xffffffffu, sv[2], off);
            sv[3] += __shfl_xor_sync(0xffffffffu, sv[3], off);
        }
        // each 8-lane group adopts one head
        float v = (gsel == 0) ? sv[0] : (gsel == 1) ? sv[1]
                : (gsel == 2) ? sv[2] : sv[3];
        // stage B: finish reduction within the 8-lane group
        v += __shfl_xor_sync(0xffffffffu, v, 4);
        v += __shfl_xor_sync(0xffffffffu, v, 2);
        v += __shfl_xor_sync(0xffffffffu, v, 1);
        // one exp per lane (covers this group's head)
        float pown = __expf(v - M_FIX);
        // broadcast all 4 head-probabilities to every lane
        float p[4];
        #pragma unroll
        for (int g = 0; g < 4; g++)
            p[g] = __shfl_sync(0xffffffffu, pown, (g << 3) | lsub);

        #pragma unroll
        for (int g = 0; g < 4; g++) {
            l[g] += p[g];
            acc[g].x = fmaf(p[g], vv.x, acc[g].x);
            acc[g].y = fmaf(p[g], vv.y, acc[g].y);
            acc[g].z = fmaf(p[g], vv.z, acc[g].z);
            acc[g].w = fmaf(p[g], vv.w, acc[g].w);
        }
        j += 64;
        it++;
    }

    if (lane == 0) {
        #pragma unroll
        for (int g = 0; g < 4; g++) sl[wid][g] = l[g];
    }
    #pragma unroll
    for (int g = 0; g < 4; g++)
        *(float4*)(&sacc[wid][g][lane * 4]) = acc[g];
    __syncthreads();

    const int g = tid >> 5;
    const int l32 = tid & 31;
    float L = 0.f;
    float4 V = make_float4(0.f, 0.f, 0.f, 0.f);
    #pragma unroll
    for (int w = 0; w < 4; w++) {
        L += sl[w][g];
        float4 a = *(const float4*)(&sacc[w][g][l32 * 4]);
        V.x += a.x; V.y += a.y; V.z += a.z; V.w += a.w;
    }
    const size_t pb = (size_t)(blk * GRP + g) * DIM;
    *(float4*)&g_pacc[pb + l32 * 4] = V;
    if (l32 == 0) g_pl[blk * GRP + g] = L;
}

// combine NSPLIT partials -> g_attn[b, h, d]. grid = B*KVH*G (1024), block 128.
__global__ void attn_reduce() {
    const int idx = blockIdx.x;
    const int g = idx & 3;
    const int kvh = (idx >> 2) & 7;
    const int b = idx >> 5;
    const int d = threadIdx.x;
    const int base = ((b * KVHEADS + kvh) * NSPLIT) * GRP + g;
    float L = 0.f, a = 0.f;
    #pragma unroll
    for (int s = 0; s < NSPLIT; s++) {
        L += g_pl[base + s * GRP];
        a += g_pacc[(size_t)(base + s * GRP) * DIM + d];
    }
    g_attn[((size_t)(b * HEADS + kvh * GRP + g) << 7) + d] = a / L;
}

// ------------------------------ launch --------------------------------------
extern "C" void kernel_launch(void* const* d_in, const int* in_sizes, int n_in,
                              void* d_out, int out_size) {
    const float* hs = (const float*)d_in[0];
    const int* pos = (const int*)d_in[1];
    const float* kc = (const float*)d_in[2];
    const float* vc = (const float*)d_in[3];
    const int* cl = (const int*)d_in[4];
    const float* wq = (const float*)d_in[5];
    const float* wo = (const float*)d_in[6];
    float* out = (float*)d_out;

    float* qbuf = nullptr;
    float* abuf = nullptr;
    cudaGetSymbolAddress((void**)&qbuf, g_q);
    cudaGetSymbolAddress((void**)&abuf, g_attn);

    // q = hs @ wq.T   (3xTF32: fp32-accurate, softmax-critical)
    gemm_tf32<<<dim3(32, KSG), 256>>>(hs, wq);
    ksum_part<<<512, 256>>>(qbuf);
    // RoPE in place
    rope_kernel<<<1024, 64>>>(pos);
    // flash-decode attention, strided split over K
    attn_kernel<<<BATCH * KVHEADS * NSPLIT, 128>>>(kc, vc, cl);
    attn_reduce<<<BATCH * KVHEADS * GRP, 128>>>();
    // out = attn @ wo.T  (1xTF32: linear on output, error unamplified)
    gemm_tf32_fast<<<dim3(32, KSG), 256>>>(abuf, wo);
    ksum_part<<<512, 256>>>(out);
}

// round 11
// speedup vs baseline: 1.8317x; 1.0871x over previous
#include <cuda_runtime.h>
#include <cstdint>
#include <math.h>

#define BATCH 32
#define HEADS 32
#define KVHEADS 8
#define DIM 128
#define KCTX 4096
#define HSZ 4096
#define GRP 4
#define NSPLIT 16
#define KSG 16                     // gemm k-splits
#define QK_SCALE 0.08838834764831845f
#define M_FIX 16.0f                // fixed softmax shift (scale-invariant)

// ------------------------------ scratch (no allocs allowed) ------------------
__device__ float g_q[BATCH * HSZ];                              // 512 KB
__device__ float g_attn[BATCH * HSZ];                           // 512 KB
__device__ float g_gpart[KSG * BATCH * HSZ];                    // 8 MB (gemm split-K partials)
__device__ float g_pacc[BATCH * KVHEADS * NSPLIT * GRP * DIM];  // 8 MB (attn partials)
__device__ float g_pl[BATCH * KVHEADS * NSPLIT * GRP];

// ------------------------------ helpers -------------------------------------
__device__ __forceinline__ unsigned f2tf(float x) {
    unsigned r;
    asm("cvt.rna.tf32.f32 %0, %1;" : "=r"(r) : "f"(x));
    return r;
}

__device__ __forceinline__ void cpasync16(void* smem_dst, const void* gsrc) {
    unsigned d = (unsigned)__cvta_generic_to_shared(smem_dst);
    asm volatile("cp.async.cg.shared.global [%0], [%1], 16;"
                 :: "r"(d), "l"(gsrc) : "memory");
}

// m16n8k8 tf32 MMA: A frag {a0..a3}, B frag {b0,b1}, fp32 accum in-place.
#define MMA8(C, Ar, B0, B1)                                                    \
    asm volatile(                                                              \
        "mma.sync.aligned.m16n8k8.row.col.f32.tf32.tf32.f32 "                  \
        "{%0,%1,%2,%3},{%4,%5,%6,%7},{%8,%9},{%0,%1,%2,%3};"                   \
        : "+f"((C)[0]), "+f"((C)[1]), "+f"((C)[2]), "+f"((C)[3])               \
        : "r"((Ar)[0]), "r"((Ar)[1]), "r"((Ar)[2]), "r"((Ar)[3]),              \
          "r"(B0), "r"(B1))

// load one 32-wide k-stage: A tile 32x32, W tile 128x32. 128 threads.
#define GEMM_LOAD_STAGE(s, kb)                                                 \
    do {                                                                       \
        _Pragma("unroll")                                                      \
        for (int r_ = 0; r_ < 2; r_++) {                                       \
            int idx_ = tid + 128 * r_;                                         \
            int ar_ = idx_ >> 3, ak_ = (idx_ & 7) * 4;                         \
            cpasync16(&As[s][ar_][ak_], A + (size_t)ar_ * HSZ + (kb) + ak_);   \
        }                                                                      \
        _Pragma("unroll")                                                      \
        for (int r_ = 0; r_ < 8; r_++) {                                       \
            int idx_ = tid + 128 * r_;                                         \
            int wr_ = idx_ >> 3, wk_ = (idx_ & 7) * 4;                         \
            cpasync16(&Ws[s][wr_][wk_],                                        \
                      W + (size_t)(n0 + wr_) * HSZ + (kb) + wk_);              \
        }                                                                      \
        asm volatile("cp.async.commit_group;" ::: "memory");                   \
    } while (0)

// ------------------------------ GEMM (3xTF32, fp32-accurate, k8) -------------
// out[b,n] = sum_k A[b,k] * W[n,k]. M=32, N=4096, K=4096.
// Grid (32 n-tiles of 128, KSG=16 k-splits), 128 thr (4 warps).
// Each warp owns m32 x n32 (2 m16-halves x 4 n8-tiles); k8 MMAs.
// D = Ah*Bh + Al*Bh + Ah*Bl (fp32 accum) ~ fp32. Used for wq (softmax-critical).
__global__ __launch_bounds__(128) void gemm_tf32(const float* __restrict__ A,
                                                 const float* __restrict__ W) {
    __shared__ float As[2][32][36];
    __shared__ float Ws[2][128][36];
    const int tid = threadIdx.x;
    const int ng = tid >> 5;           // n32 group (0..3)
    const int lane = tid & 31;
    const int groupID = lane >> 2;
    const int tig = lane & 3;
    const int n0 = blockIdx.x * 128;
    const int ks = blockIdx.y;
    const int kbeg = ks * (HSZ / KSG);

    float c[2][4][4] = {};             // [m-half][n8-tile][c0..c3]

    GEMM_LOAD_STAGE(0, kbeg);
    #pragma unroll 1
    for (int i = 0; i < 8; i++) {
        const int s = i & 1;
        if (i < 7) {
            GEMM_LOAD_STAGE(s ^ 1, kbeg + (i + 1) * 32);
            asm volatile("cp.async.wait_group 1;" ::: "memory");
        } else {
            asm volatile("cp.async.wait_group 0;" ::: "memory");
        }
        __syncthreads();

        #pragma unroll
        for (int k8 = 0; k8 < 4; k8++) {
            const int k = k8 * 8 + tig;
            // A fragments (hi/lo) for both m16 halves
            unsigned ah[2][4], al[2][4];
            #pragma unroll
            for (int mh = 0; mh < 2; mh++) {
                #pragma unroll
                for (int t = 0; t < 4; t++) {
                    int row = mh * 16 + groupID + (t & 1) * 8;
                    int col = k + (t >> 1) * 4;
                    float af = As[s][row][col];
                    ah[mh][t] = f2tf(af);
                    al[mh][t] = f2tf(af - __uint_as_float(ah[mh][t]));
                }
            }
            #pragma unroll
            for (int nt = 0; nt < 4; nt++) {
                int n = ng * 32 + nt * 8 + groupID;
                float b0f = Ws[s][n][k];
                float b1f = Ws[s][n][k + 4];
                unsigned bh0 = f2tf(b0f), bh1 = f2tf(b1f);
                unsigned bl0 = f2tf(b0f - __uint_as_float(bh0));
                unsigned bl1 = f2tf(b1f - __uint_as_float(bh1));
                #pragma unroll
                for (int mh = 0; mh < 2; mh++) {
                    MMA8(c[mh][nt], ah[mh], bh0, bh1);
                    MMA8(c[mh][nt], al[mh], bh0, bh1);
                    MMA8(c[mh][nt], ah[mh], bl0, bl1);
                }
            }
        }
        __syncthreads();
    }

    float* outp = g_gpart + (size_t)ks * (BATCH * HSZ);
    #pragma unroll
    for (int mh = 0; mh < 2; mh++) {
        const int m = mh * 16 + groupID;
        #pragma unroll
        for (int nt = 0; nt < 4; nt++) {
            int n = n0 + ng * 32 + nt * 8 + 2 * tig;
            *(float2*)&outp[(size_t)m * HSZ + n] =
                make_float2(c[mh][nt][0], c[mh][nt][1]);
            *(float2*)&outp[(size_t)(m + 8) * HSZ + n] =
                make_float2(c[mh][nt][2], c[mh][nt][3]);
        }
    }
}

// ------------------------------ GEMM (1xTF32, fast, k8) ----------------------
// Same tiling, single-pass tf32 (~2e-4 rel). Used for wo only (pure linear map).
__global__ __launch_bounds__(128) void gemm_tf32_fast(const float* __restrict__ A,
                                                      const float* __restrict__ W) {
    __shared__ float As[2][32][36];
    __shared__ float Ws[2][128][36];
    const int tid = threadIdx.x;
    const int ng = tid >> 5;
    const int lane = tid & 31;
    const int groupID = lane >> 2;
    const int tig = lane & 3;
    const int n0 = blockIdx.x * 128;
    const int ks = blockIdx.y;
    const int kbeg = ks * (HSZ / KSG);

    float c[2][4][4] = {};

    GEMM_LOAD_STAGE(0, kbeg);
    #pragma unroll 1
    for (int i = 0; i < 8; i++) {
        const int s = i & 1;
        if (i < 7) {
            GEMM_LOAD_STAGE(s ^ 1, kbeg + (i + 1) * 32);
            asm volatile("cp.async.wait_group 1;" ::: "memory");
        } else {
            asm volatile("cp.async.wait_group 0;" ::: "memory");
        }
        __syncthreads();

        #pragma unroll
        for (int k8 = 0; k8 < 4; k8++) {
            const int k = k8 * 8 + tig;
            unsigned ah[2][4];
            #pragma unroll
            for (int mh = 0; mh < 2; mh++) {
                #pragma unroll
                for (int t = 0; t < 4; t++) {
                    int row = mh * 16 + groupID + (t & 1) * 8;
                    int col = k + (t >> 1) * 4;
                    ah[mh][t] = f2tf(As[s][row][col]);
                }
            }
            #pragma unroll
            for (int nt = 0; nt < 4; nt++) {
                int n = ng * 32 + nt * 8 + groupID;
                unsigned bh0 = f2tf(Ws[s][n][k]);
                unsigned bh1 = f2tf(Ws[s][n][k + 4]);
                MMA8(c[0][nt], ah[0], bh0, bh1);
                MMA8(c[1][nt], ah[1], bh0, bh1);
            }
        }
        __syncthreads();
    }

    float* outp = g_gpart + (size_t)ks * (BATCH * HSZ);
    #pragma unroll
    for (int mh = 0; mh < 2; mh++) {
        const int m = mh * 16 + groupID;
        #pragma unroll
        for (int nt = 0; nt < 4; nt++) {
            int n = n0 + ng * 32 + nt * 8 + 2 * tig;
            *(float2*)&outp[(size_t)m * HSZ + n] =
                make_float2(c[mh][nt][0], c[mh][nt][1]);
            *(float2*)&outp[(size_t)(m + 8) * HSZ + n] =
                make_float2(c[mh][nt][2], c[mh][nt][3]);
        }
    }
}

// sum the KSG split-K partials into dst. 131072 elems.
__global__ void ksum_part(float* __restrict__ dst) {
    int i = blockIdx.x * blockDim.x + threadIdx.x;
    float s = 0.f;
    #pragma unroll
    for (int p = 0; p < KSG; p++) s += g_gpart[(size_t)p * (BATCH * HSZ) + i];
    dst[i] = s;
}

// ------------------------------ RoPE (in-place on g_q) ----------------------
__global__ void rope_kernel(const int* __restrict__ positions) {
    const int bh = blockIdx.x;
    const int b = bh >> 5;
    const int j = threadIdx.x;           // 0..63
    double inv = exp(-(double)j * (13.815510557964274 / 64.0));
    double ang = (double)positions[b] * inv;
    double sd, cd;
    sincos(ang, &sd, &cd);
    float c = (float)cd, s = (float)sd;
    float* qp = g_q + ((size_t)bh << 7);
    float q1 = qp[j], q2 = qp[j + 64];
    qp[j]      = q1 * c - q2 * s;
    qp[j + 64] = q2 * c + q1 * s;
}

// ------------------------------ attention ----------------------------------
// grid = B*KVH*NSPLIT (4096), block 128 (4 warps). Full warp per key.
// cp.async depth-4 smem ring per warp. q in registers. Fixed-shift softmax.
__global__ __launch_bounds__(128, 8) void attn_kernel(const float* __restrict__ kc,
                                                      const float* __restrict__ vc,
                                                      const int* __restrict__ clens) {
    const int blk = blockIdx.x;
    const int split = blk & 15;
    const int kvh = (blk >> 4) & 7;
    const int b = blk >> 7;
    const int tid = threadIdx.x;
    const int wid = tid >> 5;
    const int lane = tid & 31;

    __shared__ float4 ring[4][4][64];   // [warp][stage][K:0-31 | V:32-63]  16 KB
    __shared__ float sl[4][GRP];
    __shared__ float sacc[4][GRP][DIM]; // 8 KB

    float4 q[GRP];
    {
        const float* qg = g_q + ((size_t)(b * HEADS + kvh * GRP) << 7) + lane * 4;
        #pragma unroll
        for (int g = 0; g < GRP; g++) {
            float4 t = *(const float4*)(qg + g * DIM);
            q[g].x = t.x * QK_SCALE; q[g].y = t.y * QK_SCALE;
            q[g].z = t.z * QK_SCALE; q[g].w = t.w * QK_SCALE;
        }
    }

    const int ctx = clens[b];
    const size_t rs = (size_t)KVHEADS * DIM; // 1024 floats per key index
    const float* kp = kc + (size_t)b * KCTX * rs + (size_t)kvh * DIM + lane * 4;
    const float* vp = vc + (size_t)b * KCTX * rs + (size_t)kvh * DIM + lane * 4;

    float l[4] = {0.f, 0.f, 0.f, 0.f};
    float4 acc[4];
    #pragma unroll
    for (int g = 0; g < 4; g++) acc[g] = make_float4(0.f, 0.f, 0.f, 0.f);

    const unsigned rb =
        (unsigned)__cvta_generic_to_shared(&ring[wid][0][0]) + lane * 16u;

    const int j0 = split + 16 * wid;   // this warp's first key; stride 64
    const int gsel = lane >> 3;        // which head this 8-lane group reduces
    const int lsub = lane & 7;

    #pragma unroll
    for (int s = 0; s < 3; s++) {
        int jc = min(j0 + 64 * s, ctx - 1);
        unsigned dst = rb + s * 1024u;
        asm volatile("cp.async.cg.shared.global [%0], [%1], 16;"
                     :: "r"(dst), "l"(kp + (size_t)jc * rs) : "memory");
        asm volatile("cp.async.cg.shared.global [%0], [%1], 16;"
                     :: "r"(dst + 512u), "l"(vp + (size_t)jc * rs) : "memory");
        asm volatile("cp.async.commit_group;" ::: "memory");
    }

    int j = j0;
    int it = 0;
    while (j < ctx) {
        asm volatile("cp.async.wait_group 2;" ::: "memory");
        const int cur = it & 3;
        float4 kv = ring[wid][cur][lane];
        float4 vv = ring[wid][cur][32 + lane];

        {
            int jc = min(j + 192, ctx - 1);
            unsigned dst = rb + ((unsigned)((it + 3) & 3)) * 1024u;
            asm volatile("cp.async.cg.shared.global [%0], [%1], 16;"
                         :: "r"(dst), "l"(kp + (size_t)jc * rs) : "memory");
            asm volatile("cp.async.cg.shared.global [%0], [%1], 16;"
                         :: "r"(dst + 512u), "l"(vp + (size_t)jc * rs) : "memory");
            asm volatile("cp.async.commit_group;" ::: "memory");
        }

        float sv[4];
        #pragma unroll
        for (int g = 0; g < 4; g++)
            sv[g] = fmaf(q[g].x, kv.x, fmaf(q[g].y, kv.y,
                     fmaf(q[g].z, kv.z, q[g].w * kv.w)));

        // stage A: reduce across xor-16, xor-8 for all 4 heads
        #pragma unroll
        for (int off = 16; off >= 8; off >>= 1) {
            sv[0] += __shfl_xor_sync(0xffffffffu, sv[0], off);
            sv[1] += __shfl_xor_sync(0xffffffffu, sv[1], off);
            sv[2] += __shfl_xor_sync(0xffffffffu, sv[2], off);
            sv[3] += __shfl_xor_sync(0xffffffffu, sv[3], off);
        }
        // each 8-lane group adopts one head
        float v = (gsel == 0) ? sv[0] : (gsel == 1) ? sv[1]
                : (gsel == 2) ? sv[2] : sv[3];
        // stage B: finish reduction within the 8-lane group
        v += __shfl_xor_sync(0xffffffffu, v, 4);
        v += __shfl_xor_sync(0xffffffffu, v, 2);
        v += __shfl_xor_sync(0xffffffffu, v, 1);
        // one exp per lane (covers this group's head)
        float pown = __expf(v - M_FIX);
        // broadcast all 4 head-probabilities to every lane
        float p[4];
        #pragma unroll
        for (int g = 0; g < 4; g++)
            p[g] = __shfl_sync(0xffffffffu, pown, (g << 3) | lsub);

        #pragma unroll
        for (int g = 0; g < 4; g++) {
            l[g] += p[g];
            acc[g].x = fmaf(p[g], vv.x, acc[g].x);
            acc[g].y = fmaf(p[g], vv.y, acc[g].y);
            acc[g].z = fmaf(p[g], vv.z, acc[g].z);
            acc[g].w = fmaf(p[g], vv.w, acc[g].w);
        }
        j += 64;
        it++;
    }

    if (lane == 0) {
        #pragma unroll
        for (int g = 0; g < 4; g++) sl[wid][g] = l[g];
    }
    #pragma unroll
    for (int g = 0; g < 4; g++)
        *(float4*)(&sacc[wid][g][lane * 4]) = acc[g];
    __syncthreads();

    const int g = tid >> 5;
    const int l32 = tid & 31;
    float L = 0.f;
    float4 V = make_float4(0.f, 0.f, 0.f, 0.f);
    #pragma unroll
    for (int w = 0; w < 4; w++) {
        L += sl[w][g];
        float4 a = *(const float4*)(&sacc[w][g][l32 * 4]);
        V.x += a.x; V.y += a.y; V.z += a.z; V.w += a.w;
    }
    const size_t pb = (size_t)(blk * GRP + g) * DIM;
    *(float4*)&g_pacc[pb + l32 * 4] = V;
    if (l32 == 0) g_pl[blk * GRP + g] = L;
}

// combine NSPLIT partials -> g_attn[b, h, d]. grid = B*KVH*G (1024), block 128.
__global__ void attn_reduce() {
    const int idx = blockIdx.x;
    const int g = idx & 3;
    const int kvh = (idx >> 2) & 7;
    const int b = idx >> 5;
    const int d = threadIdx.x;
    const int base = ((b * KVHEADS + kvh) * NSPLIT) * GRP + g;
    float L = 0.f, a = 0.f;
    #pragma unroll
    for (int s = 0; s < NSPLIT; s++) {
        L += g_pl[base + s * GRP];
        a += g_pacc[(size_t)(base + s * GRP) * DIM + d];
    }
    g_attn[((size_t)(b * HEADS + kvh * GRP + g) << 7) + d] = a / L;
}

// ------------------------------ launch --------------------------------------
extern "C" void kernel_launch(void* const* d_in, const int* in_sizes, int n_in,
                              void* d_out, int out_size) {
    const float* hs = (const float*)d_in[0];
    const int* pos = (const int*)d_in[1];
    const float* kc = (const float*)d_in[2];
    const float* vc = (const float*)d_in[3];
    const int* cl = (const int*)d_in[4];
    const float* wq = (const float*)d_in[5];
    const float* wo = (const float*)d_in[6];
    float* out = (float*)d_out;

    float* qbuf = nullptr;
    float* abuf = nullptr;
    cudaGetSymbolAddress((void**)&qbuf, g_q);
    cudaGetSymbolAddress((void**)&abuf, g_attn);

    // q = hs @ wq.T   (3xTF32 k8: fp32-accurate, softmax-critical)
    gemm_tf32<<<dim3(32, KSG), 128>>>(hs, wq);
    ksum_part<<<512, 256>>>(qbuf);
    // RoPE in place
    rope_kernel<<<1024, 64>>>(pos);
    // flash-decode attention, strided split over K
    attn_kernel<<<BATCH * KVHEADS * NSPLIT, 128>>>(kc, vc, cl);
    attn_reduce<<<BATCH * KVHEADS * GRP, 128>>>();
    // out = attn @ wo.T  (1xTF32 k8: linear on output, error unamplified)
    gemm_tf32_fast<<<dim3(32, KSG), 128>>>(abuf, wo);
    ksum_part<<<512, 256>>>(out);
}

// round 12
// speedup vs baseline: 1.8599x; 1.0154x over previous
#include <cuda_runtime.h>
#include <cstdint>
#include <math.h>

#define BATCH 32
#define HEADS 32
#define KVHEADS 8
#define DIM 128
#define KCTX 4096
#define HSZ 4096
#define GRP 4
#define NSPLIT 16
#define KSG 32                     // gemm k-splits (occupancy: ~7 blocks/SM)
#define QK_SCALE 0.08838834764831845f
#define M_FIX 16.0f                // fixed softmax shift (scale-invariant)

// ------------------------------ scratch (no allocs allowed) ------------------
__device__ float g_q[BATCH * HSZ];                              // 512 KB
__device__ float g_attn[BATCH * HSZ];                           // 512 KB
__device__ float g_gpart[KSG * BATCH * HSZ];                    // 16 MB (gemm split-K partials)
__device__ float g_pacc[BATCH * KVHEADS * NSPLIT * GRP * DIM];  // 8 MB (attn partials)
__device__ float g_pl[BATCH * KVHEADS * NSPLIT * GRP];

// ------------------------------ helpers -------------------------------------
__device__ __forceinline__ unsigned f2tf(float x) {
    unsigned r;
    asm("cvt.rna.tf32.f32 %0, %1;" : "=r"(r) : "f"(x));
    return r;
}

__device__ __forceinline__ void cpasync16(void* smem_dst, const void* gsrc) {
    unsigned d = (unsigned)__cvta_generic_to_shared(smem_dst);
    asm volatile("cp.async.cg.shared.global [%0], [%1], 16;"
                 :: "r"(d), "l"(gsrc) : "memory");
}

// m16n8k8 tf32 MMA: A frag {a0..a3}, B frag {b0,b1}, fp32 accum in-place.
#define MMA8(C, Ar, B0, B1)                                                    \
    asm volatile(                                                              \
        "mma.sync.aligned.m16n8k8.row.col.f32.tf32.tf32.f32 "                  \
        "{%0,%1,%2,%3},{%4,%5,%6,%7},{%8,%9},{%0,%1,%2,%3};"                   \
        : "+f"((C)[0]), "+f"((C)[1]), "+f"((C)[2]), "+f"((C)[3])               \
        : "r"((Ar)[0]), "r"((Ar)[1]), "r"((Ar)[2]), "r"((Ar)[3]),              \
          "r"(B0), "r"(B1))

// load one 32-wide k-stage: A tile 32x32, W tile 128x32. 128 threads.
#define GEMM_LOAD_STAGE(s, kb)                                                 \
    do {                                                                       \
        _Pragma("unroll")                                                      \
        for (int r_ = 0; r_ < 2; r_++) {                                       \
            int idx_ = tid + 128 * r_;                                         \
            int ar_ = idx_ >> 3, ak_ = (idx_ & 7) * 4;                         \
            cpasync16(&As[s][ar_][ak_], A + (size_t)ar_ * HSZ + (kb) + ak_);   \
        }                                                                      \
        _Pragma("unroll")                                                      \
        for (int r_ = 0; r_ < 8; r_++) {                                       \
            int idx_ = tid + 128 * r_;                                         \
            int wr_ = idx_ >> 3, wk_ = (idx_ & 7) * 4;                         \
            cpasync16(&Ws[s][wr_][wk_],                                        \
                      W + (size_t)(n0 + wr_) * HSZ + (kb) + wk_);              \
        }                                                                      \
        asm volatile("cp.async.commit_group;" ::: "memory");                   \
    } while (0)

// ------------------------------ GEMM (3xTF32, fp32-accurate, k8) -------------
// out[b,n] = sum_k A[b,k] * W[n,k]. M=32, N=4096, K=4096.
// Grid (32 n-tiles of 128, KSG=32 k-splits), 128 thr (4 warps).
// Each warp owns m32 x n32 (2 m16-halves x 4 n8-tiles); k8 MMAs.
// D = Ah*Bh + Al*Bh + Ah*Bl (fp32 accum) ~ fp32. Used for wq (softmax-critical).
__global__ __launch_bounds__(128) void gemm_tf32(const float* __restrict__ A,
                                                 const float* __restrict__ W) {
    __shared__ float As[2][32][36];
    __shared__ float Ws[2][128][36];
    const int tid = threadIdx.x;
    const int ng = tid >> 5;           // n32 group (0..3)
    const int lane = tid & 31;
    const int groupID = lane >> 2;
    const int tig = lane & 3;
    const int n0 = blockIdx.x * 128;
    const int ks = blockIdx.y;
    const int kbeg = ks * (HSZ / KSG); // 128-wide k chunk, 4 stages of 32

    float c[2][4][4] = {};             // [m-half][n8-tile][c0..c3]

    GEMM_LOAD_STAGE(0, kbeg);
    #pragma unroll 1
    for (int i = 0; i < 4; i++) {
        const int s = i & 1;
        if (i < 3) {
            GEMM_LOAD_STAGE(s ^ 1, kbeg + (i + 1) * 32);
            asm volatile("cp.async.wait_group 1;" ::: "memory");
        } else {
            asm volatile("cp.async.wait_group 0;" ::: "memory");
        }
        __syncthreads();

        #pragma unroll
        for (int k8 = 0; k8 < 4; k8++) {
            const int k = k8 * 8 + tig;
            unsigned ah[2][4], al[2][4];
            #pragma unroll
            for (int mh = 0; mh < 2; mh++) {
                #pragma unroll
                for (int t = 0; t < 4; t++) {
                    int row = mh * 16 + groupID + (t & 1) * 8;
                    int col = k + (t >> 1) * 4;
                    float af = As[s][row][col];
                    ah[mh][t] = f2tf(af);
                    al[mh][t] = f2tf(af - __uint_as_float(ah[mh][t]));
                }
            }
            #pragma unroll
            for (int nt = 0; nt < 4; nt++) {
                int n = ng * 32 + nt * 8 + groupID;
                float b0f = Ws[s][n][k];
                float b1f = Ws[s][n][k + 4];
                unsigned bh0 = f2tf(b0f), bh1 = f2tf(b1f);
                unsigned bl0 = f2tf(b0f - __uint_as_float(bh0));
                unsigned bl1 = f2tf(b1f - __uint_as_float(bh1));
                #pragma unroll
                for (int mh = 0; mh < 2; mh++) {
                    MMA8(c[mh][nt], ah[mh], bh0, bh1);
                    MMA8(c[mh][nt], al[mh], bh0, bh1);
                    MMA8(c[mh][nt], ah[mh], bl0, bl1);
                }
            }
        }
        __syncthreads();
    }

    float* outp = g_gpart + (size_t)ks * (BATCH * HSZ);
    #pragma unroll
    for (int mh = 0; mh < 2; mh++) {
        const int m = mh * 16 + groupID;
        #pragma unroll
        for (int nt = 0; nt < 4; nt++) {
            int n = n0 + ng * 32 + nt * 8 + 2 * tig;
            *(float2*)&outp[(size_t)m * HSZ + n] =
                make_float2(c[mh][nt][0], c[mh][nt][1]);
            *(float2*)&outp[(size_t)(m + 8) * HSZ + n] =
                make_float2(c[mh][nt][2], c[mh][nt][3]);
        }
    }
}

// ------------------------------ GEMM (1xTF32, fast, k8) ----------------------
// Same tiling, single-pass tf32 (~2e-4 rel). Used for wo only (pure linear map).
__global__ __launch_bounds__(128) void gemm_tf32_fast(const float* __restrict__ A,
                                                      const float* __restrict__ W) {
    __shared__ float As[2][32][36];
    __shared__ float Ws[2][128][36];
    const int tid = threadIdx.x;
    const int ng = tid >> 5;
    const int lane = tid & 31;
    const int groupID = lane >> 2;
    const int tig = lane & 3;
    const int n0 = blockIdx.x * 128;
    const int ks = blockIdx.y;
    const int kbeg = ks * (HSZ / KSG);

    float c[2][4][4] = {};

    GEMM_LOAD_STAGE(0, kbeg);
    #pragma unroll 1
    for (int i = 0; i < 4; i++) {
        const int s = i & 1;
        if (i < 3) {
            GEMM_LOAD_STAGE(s ^ 1, kbeg + (i + 1) * 32);
            asm volatile("cp.async.wait_group 1;" ::: "memory");
        } else {
            asm volatile("cp.async.wait_group 0;" ::: "memory");
        }
        __syncthreads();

        #pragma unroll
        for (int k8 = 0; k8 < 4; k8++) {
            const int k = k8 * 8 + tig;
            unsigned ah[2][4];
            #pragma unroll
            for (int mh = 0; mh < 2; mh++) {
                #pragma unroll
                for (int t = 0; t < 4; t++) {
                    int row = mh * 16 + groupID + (t & 1) * 8;
                    int col = k + (t >> 1) * 4;
                    ah[mh][t] = f2tf(As[s][row][col]);
                }
            }
            #pragma unroll
            for (int nt = 0; nt < 4; nt++) {
                int n = ng * 32 + nt * 8 + groupID;
                unsigned bh0 = f2tf(Ws[s][n][k]);
                unsigned bh1 = f2tf(Ws[s][n][k + 4]);
                MMA8(c[0][nt], ah[0], bh0, bh1);
                MMA8(c[1][nt], ah[1], bh0, bh1);
            }
        }
        __syncthreads();
    }

    float* outp = g_gpart + (size_t)ks * (BATCH * HSZ);
    #pragma unroll
    for (int mh = 0; mh < 2; mh++) {
        const int m = mh * 16 + groupID;
        #pragma unroll
        for (int nt = 0; nt < 4; nt++) {
            int n = n0 + ng * 32 + nt * 8 + 2 * tig;
            *(float2*)&outp[(size_t)m * HSZ + n] =
                make_float2(c[mh][nt][0], c[mh][nt][1]);
            *(float2*)&outp[(size_t)(m + 8) * HSZ + n] =
                make_float2(c[mh][nt][2], c[mh][nt][3]);
        }
    }
}

// sum the KSG split-K partials into dst. 131072 elems.
__global__ void ksum_part(float* __restrict__ dst) {
    int i = blockIdx.x * blockDim.x + threadIdx.x;
    float s = 0.f;
    #pragma unroll
    for (int p = 0; p < KSG; p++) s += g_gpart[(size_t)p * (BATCH * HSZ) + i];
    dst[i] = s;
}

// ------------------ fused split-K sum + RoPE -> g_q --------------------------
// grid = B*H (1024), block = 64 (one thread per rotation pair).
// Sums the 32 wq partials for q[bh][j] and q[bh][j+64], then rotates.
__global__ void ksum_rope(const int* __restrict__ positions) {
    const int bh = blockIdx.x;
    const int b = bh >> 5;
    const int j = threadIdx.x;           // 0..63
    const size_t base = (size_t)bh << 7; // row offset in [B*HSZ]

    float q1 = 0.f, q2 = 0.f;
    #pragma unroll
    for (int p = 0; p < KSG; p++) {
        const float* gp = g_gpart + (size_t)p * (BATCH * HSZ) + base;
        q1 += gp[j];
        q2 += gp[j + 64];
    }

    double inv = exp(-(double)j * (13.815510557964274 / 64.0));
    double ang = (double)positions[b] * inv;
    double sd, cd;
    sincos(ang, &sd, &cd);
    float c = (float)cd, s = (float)sd;
    float* qp = g_q + base;
    qp[j]      = q1 * c - q2 * s;
    qp[j + 64] = q2 * c + q1 * s;
}

// ------------------------------ attention ----------------------------------
// grid = B*KVH*NSPLIT (4096), block 128 (4 warps). Full warp per key.
// cp.async depth-4 smem ring per warp. q in registers. Fixed-shift softmax.
__global__ __launch_bounds__(128, 8) void attn_kernel(const float* __restrict__ kc,
                                                      const float* __restrict__ vc,
                                                      const int* __restrict__ clens) {
    const int blk = blockIdx.x;
    const int split = blk & 15;
    const int kvh = (blk >> 4) & 7;
    const int b = blk >> 7;
    const int tid = threadIdx.x;
    const int wid = tid >> 5;
    const int lane = tid & 31;

    __shared__ float4 ring[4][4][64];   // [warp][stage][K:0-31 | V:32-63]  16 KB
    __shared__ float sl[4][GRP];
    __shared__ float sacc[4][GRP][DIM]; // 8 KB

    float4 q[GRP];
    {
        const float* qg = g_q + ((size_t)(b * HEADS + kvh * GRP) << 7) + lane * 4;
        #pragma unroll
        for (int g = 0; g < GRP; g++) {
            float4 t = *(const float4*)(qg + g * DIM);
            q[g].x = t.x * QK_SCALE; q[g].y = t.y * QK_SCALE;
            q[g].z = t.z * QK_SCALE; q[g].w = t.w * QK_SCALE;
        }
    }

    const int ctx = clens[b];
    const size_t rs = (size_t)KVHEADS * DIM; // 1024 floats per key index
    const float* kp = kc + (size_t)b * KCTX * rs + (size_t)kvh * DIM + lane * 4;
    const float* vp = vc + (size_t)b * KCTX * rs + (size_t)kvh * DIM + lane * 4;

    float l[4] = {0.f, 0.f, 0.f, 0.f};
    float4 acc[4];
    #pragma unroll
    for (int g = 0; g < 4; g++) acc[g] = make_float4(0.f, 0.f, 0.f, 0.f);

    const unsigned rb =
        (unsigned)__cvta_generic_to_shared(&ring[wid][0][0]) + lane * 16u;

    const int j0 = split + 16 * wid;   // this warp's first key; stride 64
    const int gsel = lane >> 3;        // which head this 8-lane group reduces
    const int lsub = lane & 7;

    #pragma unroll
    for (int s = 0; s < 3; s++) {
        int jc = min(j0 + 64 * s, ctx - 1);
        unsigned dst = rb + s * 1024u;
        asm volatile("cp.async.cg.shared.global [%0], [%1], 16;"
                     :: "r"(dst), "l"(kp + (size_t)jc * rs) : "memory");
        asm volatile("cp.async.cg.shared.global [%0], [%1], 16;"
                     :: "r"(dst + 512u), "l"(vp + (size_t)jc * rs) : "memory");
        asm volatile("cp.async.commit_group;" ::: "memory");
    }

    int j = j0;
    int it = 0;
    while (j < ctx) {
        asm volatile("cp.async.wait_group 2;" ::: "memory");
        const int cur = it & 3;
        float4 kv = ring[wid][cur][lane];
        float4 vv = ring[wid][cur][32 + lane];

        {
            int jc = min(j + 192, ctx - 1);
            unsigned dst = rb + ((unsigned)((it + 3) & 3)) * 1024u;
            asm volatile("cp.async.cg.shared.global [%0], [%1], 16;"
                         :: "r"(dst), "l"(kp + (size_t)jc * rs) : "memory");
            asm volatile("cp.async.cg.shared.global [%0], [%1], 16;"
                         :: "r"(dst + 512u), "l"(vp + (size_t)jc * rs) : "memory");
            asm volatile("cp.async.commit_group;" ::: "memory");
        }

        float sv[4];
        #pragma unroll
        for (int g = 0; g < 4; g++)
            sv[g] = fmaf(q[g].x, kv.x, fmaf(q[g].y, kv.y,
                     fmaf(q[g].z, kv.z, q[g].w * kv.w)));

        // stage A: reduce across xor-16, xor-8 for all 4 heads
        #pragma unroll
        for (int off = 16; off >= 8; off >>= 1) {
            sv[0] += __shfl_xor_sync(0xffffffffu, sv[0], off);
            sv[1] += __shfl_xor_sync(0xffffffffu, sv[1], off);
            sv[2] += __shfl_xor_sync(0xffffffffu, sv[2], off);
            sv[3] += __shfl_xor_sync(0xffffffffu, sv[3], off);
        }
        // each 8-lane group adopts one head
        float v = (gsel == 0) ? sv[0] : (gsel == 1) ? sv[1]
                : (gsel == 2) ? sv[2] : sv[3];
        v += __shfl_xor_sync(0xffffffffu, v, 4);
        v += __shfl_xor_sync(0xffffffffu, v, 2);
        v += __shfl_xor_sync(0xffffffffu, v, 1);
        float pown = __expf(v - M_FIX);
        float p[4];
        #pragma unroll
        for (int g = 0; g < 4; g++)
            p[g] = __shfl_sync(0xffffffffu, pown, (g << 3) | lsub);

        #pragma unroll
        for (int g = 0; g < 4; g++) {
            l[g] += p[g];
            acc[g].x = fmaf(p[g], vv.x, acc[g].x);
            acc[g].y = fmaf(p[g], vv.y, acc[g].y);
            acc[g].z = fmaf(p[g], vv.z, acc[g].z);
            acc[g].w = fmaf(p[g], vv.w, acc[g].w);
        }
        j += 64;
        it++;
    }

    if (lane == 0) {
        #pragma unroll
        for (int g = 0; g < 4; g++) sl[wid][g] = l[g];
    }
    #pragma unroll
    for (int g = 0; g < 4; g++)
        *(float4*)(&sacc[wid][g][lane * 4]) = acc[g];
    __syncthreads();

    const int g = tid >> 5;
    const int l32 = tid & 31;
    float L = 0.f;
    float4 V = make_float4(0.f, 0.f, 0.f, 0.f);
    #pragma unroll
    for (int w = 0; w < 4; w++) {
        L += sl[w][g];
        float4 a = *(const float4*)(&sacc[w][g][l32 * 4]);
        V.x += a.x; V.y += a.y; V.z += a.z; V.w += a.w;
    }
    const size_t pb = (size_t)(blk * GRP + g) * DIM;
    *(float4*)&g_pacc[pb + l32 * 4] = V;
    if (l32 == 0) g_pl[blk * GRP + g] = L;
}

// combine NSPLIT partials -> g_attn[b, h, d]. grid = B*KVH*G (1024), block 128.
__global__ void attn_reduce() {
    const int idx = blockIdx.x;
    const int g = idx & 3;
    const int kvh = (idx >> 2) & 7;
    const int b = idx >> 5;
    const int d = threadIdx.x;
    const int base = ((b * KVHEADS + kvh) * NSPLIT) * GRP + g;
    float L = 0.f, a = 0.f;
    #pragma unroll
    for (int s = 0; s < NSPLIT; s++) {
        L += g_pl[base + s * GRP];
        a += g_pacc[(size_t)(base + s * GRP) * DIM + d];
    }
    g_attn[((size_t)(b * HEADS + kvh * GRP + g) << 7) + d] = a / L;
}

// ------------------------------ launch --------------------------------------
extern "C" void kernel_launch(void* const* d_in, const int* in_sizes, int n_in,
                              void* d_out, int out_size) {
    const float* hs = (const float*)d_in[0];
    const int* pos = (const int*)d_in[1];
    const float* kc = (const float*)d_in[2];
    const float* vc = (const float*)d_in[3];
    const int* cl = (const int*)d_in[4];
    const float* wq = (const float*)d_in[5];
    const float* wo = (const float*)d_in[6];
    float* out = (float*)d_out;

    float* abuf = nullptr;
    cudaGetSymbolAddress((void**)&abuf, g_attn);

    // q = rope(hs @ wq.T)   (3xTF32 k8, split-K 32; fused sum+rope)
    gemm_tf32<<<dim3(32, KSG), 128>>>(hs, wq);
    ksum_rope<<<1024, 64>>>(pos);
    // flash-decode attention, strided split over K
    attn_kernel<<<BATCH * KVHEADS * NSPLIT, 128>>>(kc, vc, cl);
    attn_reduce<<<BATCH * KVHEADS * GRP, 128>>>();
    // out = attn @ wo.T  (1xTF32 k8: linear on output, error unamplified)
    gemm_tf32_fast<<<dim3(32, KSG), 128>>>(abuf, wo);
    ksum_part<<<512, 256>>>(out);
}